// round 1
// baseline (speedup 1.0000x reference)
#include <cuda_runtime.h>
#include <cuda_bf16.h>
#include <math.h>

#define D 128
#define R 16
#define NCOL 2176   // R*D + D  (relation GEMM columns + self columns)

// ---------------- scratch (device globals; allocation-free) ----------------
__device__ float g_trans[108800000];          // 50000 * 2176
__device__ float g_agg[6400000];              // 50000 * 128
__device__ float g_x[6400000];                // 50000 * 128
__device__ float g_deg[50000];
__device__ float g_B[128 * NCOL];             // packed weights, [d][j]
__device__ float g_seq[256 * 4 * 256];        // (P, L, 2D)
__device__ float g_WT[2][384 * 512];          // transposed LSTM weights [dir][d][j]
__device__ float g_h[2 * 256 * 128];          // final hidden states [dir][p][k]

// ---------------- small utility kernels ----------------
__global__ void k_zero_deg(int N) {
    int i = blockIdx.x * blockDim.x + threadIdx.x;
    if (i < N) g_deg[i] = 0.0f;
}

__global__ void k_zero_agg(int total) {
    int i = blockIdx.x * blockDim.x + threadIdx.x;
    if (i < total) g_agg[i] = 0.0f;
}

__global__ void k_deg(const int* __restrict__ dst, int E) {
    int e = blockIdx.x * blockDim.x + threadIdx.x;
    if (e < E) atomicAdd(&g_deg[dst[e]], 1.0f);
}

// pack W_rel[l] (R,D,D) and W_self[l] (D,D) into B[d][j], j = r*128+k for j<2048, else self col
__global__ void k_pack(const float* __restrict__ Wrel, const float* __restrict__ Wself) {
    int idx = blockIdx.x * blockDim.x + threadIdx.x;
    if (idx >= 128 * NCOL) return;
    int d = idx / NCOL, j = idx % NCOL;
    float v;
    if (j < 2048) {
        int r = j >> 7, k = j & 127;
        v = Wrel[(size_t)r * (128 * 128) + d * 128 + k];
    } else {
        v = Wself[d * 128 + (j - 2048)];
    }
    g_B[idx] = v;
}

// ---------------- main GEMM: C(M x 2176) = A(M x 128) @ B(128 x 2176) ----------------
// 128x128 block tile, 256 threads, 8x8 microtile, K staged in 16-chunks.
__global__ __launch_bounds__(256) void k_gemm(const float* __restrict__ x0, int layer, int M) {
    const float* A = (layer == 0) ? x0 : (const float*)g_x;
    __shared__ float As[16][128];   // [k][m]
    __shared__ float Bs[16][128];   // [k][n]
    int bn = blockIdx.x, bm = blockIdx.y;
    int m0 = bm * 128, n0 = bn * 128;
    int t = threadIdx.x;
    int tx = t & 15, ty = t >> 4;
    float acc[8][8];
#pragma unroll
    for (int i = 0; i < 8; i++)
#pragma unroll
        for (int j = 0; j < 8; j++) acc[i][j] = 0.0f;

    for (int kc = 0; kc < 128; kc += 16) {
        // load A tile (128 rows x 16 k), transposed into As[k][m]
#pragma unroll
        for (int r = 0; r < 2; r++) {
            int q = t + r * 256;            // 0..511 float4 slots
            int row = q >> 2, kq = (q & 3) * 4;
            float4 v = make_float4(0.f, 0.f, 0.f, 0.f);
            int gm = m0 + row;
            if (gm < M) v = *(const float4*)(A + (size_t)gm * 128 + kc + kq);
            As[kq + 0][row] = v.x; As[kq + 1][row] = v.y;
            As[kq + 2][row] = v.z; As[kq + 3][row] = v.w;
        }
        // load B tile (16 k x 128 n)
#pragma unroll
        for (int r = 0; r < 2; r++) {
            int q = t + r * 256;
            int krow = q >> 5, j4 = (q & 31) * 4;
            float4 v = *(const float4*)(g_B + (size_t)(kc + krow) * NCOL + n0 + j4);
            *(float4*)(&Bs[krow][j4]) = v;
        }
        __syncthreads();
#pragma unroll
        for (int kk = 0; kk < 16; kk++) {
            float4 a0 = *(const float4*)(&As[kk][ty * 8]);
            float4 a1 = *(const float4*)(&As[kk][ty * 8 + 4]);
            float4 b0 = *(const float4*)(&Bs[kk][tx * 8]);
            float4 b1 = *(const float4*)(&Bs[kk][tx * 8 + 4]);
            float a[8] = {a0.x, a0.y, a0.z, a0.w, a1.x, a1.y, a1.z, a1.w};
            float b[8] = {b0.x, b0.y, b0.z, b0.w, b1.x, b1.y, b1.z, b1.w};
#pragma unroll
            for (int i = 0; i < 8; i++)
#pragma unroll
                for (int j = 0; j < 8; j++)
                    acc[i][j] = fmaf(a[i], b[j], acc[i][j]);
        }
        __syncthreads();
    }
#pragma unroll
    for (int i = 0; i < 8; i++) {
        int gm = m0 + ty * 8 + i;
        if (gm < M) {
#pragma unroll
            for (int j = 0; j < 8; j += 4) {
                float4 v = make_float4(acc[i][j], acc[i][j + 1], acc[i][j + 2], acc[i][j + 3]);
                *(float4*)(g_trans + (size_t)gm * NCOL + n0 + tx * 8 + j) = v;
            }
        }
    }
}

// ---------------- edge scatter: agg[dst] += trans[src][etype*128 + :] ----------------
__global__ void k_scatter(const int* __restrict__ src, const int* __restrict__ dst,
                          const int* __restrict__ et, int E) {
    int gw = (blockIdx.x * blockDim.x + threadIdx.x) >> 5;
    int lane = threadIdx.x & 31;
    if (gw >= E) return;
    int s = src[gw], dd = dst[gw], r = et[gw];
    float4 v = *(const float4*)(g_trans + (size_t)s * NCOL + r * 128 + lane * 4);
    float* ap = g_agg + (size_t)dd * 128 + lane * 4;
    atomicAdd(ap + 0, v.x);
    atomicAdd(ap + 1, v.y);
    atomicAdd(ap + 2, v.z);
    atomicAdd(ap + 3, v.w);
}

// ---------------- node update: relu(self + b + agg/denom) then LayerNorm ----------------
__global__ void k_update(const float* __restrict__ bself, const float* __restrict__ g,
                         const float* __restrict__ b, float* __restrict__ enc_out,
                         int layer, int M) {
    int n = blockIdx.x;
    int d = threadIdx.x;  // 128 threads
    if (n >= M) return;
    float denom = fmaxf(g_deg[n], 1.0f);
    float v = g_trans[(size_t)n * NCOL + 2048 + d] + bself[d] + g_agg[(size_t)n * 128 + d] / denom;
    v = fmaxf(v, 0.0f);

    __shared__ float red1[4], red2[4];
    float s = v;
#pragma unroll
    for (int o = 16; o > 0; o >>= 1) s += __shfl_xor_sync(0xFFFFFFFFu, s, o);
    if ((d & 31) == 0) red1[d >> 5] = s;
    __syncthreads();
    float mu = (red1[0] + red1[1] + red1[2] + red1[3]) * (1.0f / 128.0f);
    float dv = v - mu;
    float q = dv * dv;
#pragma unroll
    for (int o = 16; o > 0; o >>= 1) q += __shfl_xor_sync(0xFFFFFFFFu, q, o);
    if ((d & 31) == 0) red2[d >> 5] = q;
    __syncthreads();
    float var = (red2[0] + red2[1] + red2[2] + red2[3]) * (1.0f / 128.0f);
    float out = dv * rsqrtf(var + 1e-5f) * g[d] + b[d];
    if (layer == 0) g_x[(size_t)n * 128 + d] = out;
    else            enc_out[(size_t)n * 128 + d] = out;
}

// ---------------- build LSTM input sequence ----------------
__global__ void k_seq(const float* __restrict__ enc, const int* __restrict__ pn,
                      const int* __restrict__ pr, const float* __restrict__ rel) {
    int pl = blockIdx.x;          // P*L blocks
    int p = pl >> 2, t = pl & 3;
    int d = threadIdx.x;          // 128
    int node = pn[p * 4 + t];
    float* o = g_seq + ((size_t)p * 4 + t) * 256;
    o[d] = enc[(size_t)node * 128 + d];
    float rv = 0.0f;
    if (t > 0) { int r = pr[p * 3 + (t - 1)]; rv = rel[r * 128 + d]; }
    o[128 + d] = rv;
}

// transpose LSTM weights: WT[dir][d][j], d<256 from W_ih[j][d], d>=256 from W_hh[j][d-256]
__global__ void k_wt(const float* __restrict__ Wih_f, const float* __restrict__ Whh_f,
                     const float* __restrict__ Wih_b, const float* __restrict__ Whh_b) {
    int idx = blockIdx.x * blockDim.x + threadIdx.x;
    if (idx >= 2 * 384 * 512) return;
    int dir = idx / (384 * 512);
    int rem = idx % (384 * 512);
    int d = rem / 512, j = rem % 512;
    const float* Wih = dir ? Wih_b : Wih_f;
    const float* Whh = dir ? Whh_b : Whh_f;
    float v = (d < 256) ? Wih[j * 256 + d] : Whh[j * 128 + (d - 256)];
    g_WT[dir][rem] = v;
}

// ---------------- bidirectional LSTM (8 paths per block) ----------------
__global__ __launch_bounds__(512) void k_lstm(const float* __restrict__ bf,
                                              const float* __restrict__ bb) {
    const int PB = 8;
    __shared__ float xt[PB][256];
    __shared__ float hs[PB][128];
    __shared__ float cs[PB][128];
    __shared__ float gs[PB][512];
    int dir = blockIdx.y;
    const float* WT = g_WT[dir];
    const float* bias = dir ? bb : bf;
    int p0 = blockIdx.x * PB;
    int t = threadIdx.x;   // 512 threads; thread t owns gate column t

    for (int i = t; i < PB * 128; i += 512) { ((float*)hs)[i] = 0.0f; ((float*)cs)[i] = 0.0f; }
    float bj = bias[t];
    __syncthreads();

    for (int step = 0; step < 4; step++) {
        int tt = dir ? (3 - step) : step;
        for (int i = t; i < PB * 256; i += 512) {
            int pp = i >> 8, d = i & 255;
            xt[pp][d] = g_seq[((size_t)(p0 + pp) * 4 + tt) * 256 + d];
        }
        __syncthreads();
        float acc[PB];
#pragma unroll
        for (int p = 0; p < PB; p++) acc[p] = bj;
        for (int d = 0; d < 256; d++) {
            float w = WT[d * 512 + t];
#pragma unroll
            for (int p = 0; p < PB; p++) acc[p] = fmaf(w, xt[p][d], acc[p]);
        }
        for (int d = 0; d < 128; d++) {
            float w = WT[(256 + d) * 512 + t];
#pragma unroll
            for (int p = 0; p < PB; p++) acc[p] = fmaf(w, hs[p][d], acc[p]);
        }
#pragma unroll
        for (int p = 0; p < PB; p++) gs[p][t] = acc[p];
        __syncthreads();
        // gate order i,f,g,o
        for (int i = t; i < PB * 128; i += 512) {
            int pp = i >> 7, k = i & 127;
            float ig = 1.0f / (1.0f + expf(-gs[pp][k]));
            float fg = 1.0f / (1.0f + expf(-gs[pp][128 + k]));
            float gg = tanhf(gs[pp][256 + k]);
            float og = 1.0f / (1.0f + expf(-gs[pp][384 + k]));
            float c = fg * cs[pp][k] + ig * gg;
            cs[pp][k] = c;
            hs[pp][k] = og * tanhf(c);
        }
        __syncthreads();
    }
    for (int i = t; i < PB * 128; i += 512) {
        int pp = i >> 7, k = i & 127;
        g_h[((size_t)dir * 256 + p0 + pp) * 128 + k] = hs[pp][k];
    }
}

// ---------------- output head: pe = relu(cat(hf,hb)@Wop.T + bop); sim scorer ----------------
__global__ void k_head(const float* __restrict__ Wop, const float* __restrict__ bop,
                       const float* __restrict__ q, const float* __restrict__ Ws1,
                       const float* __restrict__ bs1, const float* __restrict__ Ws2,
                       const float* __restrict__ bs2,
                       float* __restrict__ pe_out, float* __restrict__ sim_out) {
    int p = blockIdx.x;
    int k = threadIdx.x;   // 128
    __shared__ float cat[256];
    __shared__ float cat2[256];
    __shared__ float red[4];
    cat[k]       = g_h[(size_t)p * 128 + k];          // forward h
    cat[128 + k] = g_h[(size_t)(256 + p) * 128 + k];  // backward h
    __syncthreads();
    float acc = bop[k];
    for (int j = 0; j < 256; j++) acc = fmaf(cat[j], Wop[k * 256 + j], acc);
    float pe = fmaxf(acc, 0.0f);
    pe_out[(size_t)p * 128 + k] = pe;
    cat2[k] = pe;
    cat2[128 + k] = q[k];
    __syncthreads();
    float a2 = bs1[k];
    for (int j = 0; j < 256; j++) a2 = fmaf(cat2[j], Ws1[k * 256 + j], a2);
    float hdn = fmaxf(a2, 0.0f);
    float s = hdn * Ws2[k];
#pragma unroll
    for (int o = 16; o > 0; o >>= 1) s += __shfl_xor_sync(0xFFFFFFFFu, s, o);
    if ((k & 31) == 0) red[k >> 5] = s;
    __syncthreads();
    if (k == 0) {
        float tot = red[0] + red[1] + red[2] + red[3] + bs2[0];
        sim_out[p] = 1.0f / (1.0f + expf(-tot));
    }
}

// ---------------- launch ----------------
extern "C" void kernel_launch(void* const* d_in, const int* in_sizes, int n_in,
                              void* d_out, int out_size) {
    const float* node_features = (const float*)d_in[0];
    const int*   edge_index    = (const int*)d_in[1];
    const int*   edge_types    = (const int*)d_in[2];
    const float* query         = (const float*)d_in[3];
    const int*   path_nodes    = (const int*)d_in[4];
    const int*   path_rel      = (const int*)d_in[5];
    const float* W_self        = (const float*)d_in[6];
    const float* b_self        = (const float*)d_in[7];
    const float* W_rel         = (const float*)d_in[8];
    const float* ln_g          = (const float*)d_in[9];
    const float* ln_b          = (const float*)d_in[10];
    const float* rel_emb       = (const float*)d_in[11];
    const float* W_ih_f        = (const float*)d_in[12];
    const float* W_hh_f        = (const float*)d_in[13];
    const float* b_f           = (const float*)d_in[14];
    const float* W_ih_b        = (const float*)d_in[15];
    const float* W_hh_b        = (const float*)d_in[16];
    const float* b_b           = (const float*)d_in[17];
    const float* W_op          = (const float*)d_in[18];
    const float* b_op          = (const float*)d_in[19];
    const float* W_s1          = (const float*)d_in[20];
    const float* b_s1          = (const float*)d_in[21];
    const float* W_s2          = (const float*)d_in[22];
    const float* b_s2          = (const float*)d_in[23];
    (void)n_in; (void)out_size;

    const int N = in_sizes[0] / 128;   // 50000
    const int E = in_sizes[1] / 2;     // 800000
    const int P = in_sizes[4] / 4;     // 256

    float* out     = (float*)d_out;
    float* enc_out = out;
    float* pe_out  = out + (size_t)N * 128;
    float* sim_out = pe_out + (size_t)P * 128;

    const int* src = edge_index;
    const int* dst = edge_index + E;

    k_zero_deg<<<(N + 255) / 256, 256>>>(N);
    k_deg<<<(E + 255) / 256, 256>>>(dst, E);

    for (int l = 0; l < 2; l++) {
        k_pack<<<(128 * NCOL + 255) / 256, 256>>>(W_rel + (size_t)l * R * 128 * 128,
                                                  W_self + (size_t)l * 128 * 128);
        dim3 ggrid(NCOL / 128, (N + 127) / 128);
        k_gemm<<<ggrid, 256>>>(node_features, l, N);
        k_zero_agg<<<(N * 128 + 255) / 256, 256>>>(N * 128);
        k_scatter<<<(E + 7) / 8, 256>>>(src, dst, edge_types, E);
        k_update<<<N, 128>>>(b_self + l * 128, ln_g + l * 128, ln_b + l * 128,
                             enc_out, l, N);
    }

    k_seq<<<P * 4, 128>>>(enc_out, path_nodes, path_rel, rel_emb);
    k_wt<<<(2 * 384 * 512 + 255) / 256, 256>>>(W_ih_f, W_hh_f, W_ih_b, W_hh_b);
    k_lstm<<<dim3(P / 8, 2), 512>>>(b_f, b_b);
    k_head<<<P, 128>>>(W_op, b_op, query, W_s1, b_s1, W_s2, b_s2, pe_out, sim_out);
}

// round 3
// speedup vs baseline: 1.6821x; 1.6821x over previous
#include <cuda_runtime.h>
#include <cuda_fp16.h>
#include <math.h>
#include <stdint.h>

#define D 128
#define R 16
#define NCOL 2176          // R*D + D
#define MPAD 50048         // 391 * 128

// ---------------- scratch (device globals; allocation-free) ----------------
__device__ float g_trans[(size_t)MPAD * NCOL];     // 435 MB
__device__ float g_agg[(size_t)MPAD * 128];
__device__ float g_x[(size_t)MPAD * 128];
__device__ float g_deg[50000];
__device__ __half g_Ah[(size_t)MPAD * 128];
__device__ __half g_Al[(size_t)MPAD * 128];
__device__ __half g_Bh[NCOL * 128];                 // [n][k]
__device__ __half g_Bl[NCOL * 128];
__device__ float g_seq[256 * 4 * 256];
__device__ float g_WT[2][384 * 512];
__device__ float g_h[2 * 256 * 128];

// ---------------- PTX helpers ----------------
__device__ __forceinline__ uint32_t smem_u32(const void* p) {
    return (uint32_t)__cvta_generic_to_shared(p);
}
__device__ __forceinline__ void ldm_x4(uint32_t& r0, uint32_t& r1, uint32_t& r2, uint32_t& r3,
                                       uint32_t a) {
    asm volatile("ldmatrix.sync.aligned.m8n8.x4.shared.b16 {%0,%1,%2,%3}, [%4];"
                 : "=r"(r0), "=r"(r1), "=r"(r2), "=r"(r3) : "r"(a));
}
__device__ __forceinline__ void ldm_x2(uint32_t& r0, uint32_t& r1, uint32_t a) {
    asm volatile("ldmatrix.sync.aligned.m8n8.x2.shared.b16 {%0,%1}, [%2];"
                 : "=r"(r0), "=r"(r1) : "r"(a));
}
__device__ __forceinline__ void mma16816(float* c, uint32_t a0, uint32_t a1, uint32_t a2,
                                         uint32_t a3, uint32_t b0, uint32_t b1) {
    asm volatile(
        "mma.sync.aligned.m16n8k16.row.col.f32.f16.f16.f32 "
        "{%0,%1,%2,%3}, {%4,%5,%6,%7}, {%8,%9}, {%0,%1,%2,%3};"
        : "+f"(c[0]), "+f"(c[1]), "+f"(c[2]), "+f"(c[3])
        : "r"(a0), "r"(a1), "r"(a2), "r"(a3), "r"(b0), "r"(b1));
}

// ---------------- small utility kernels ----------------
__global__ void k_zero_deg(int N) {
    int i = blockIdx.x * blockDim.x + threadIdx.x;
    if (i < N) g_deg[i] = 0.0f;
}
__global__ void k_zero_agg(int total) {
    int i = blockIdx.x * blockDim.x + threadIdx.x;
    if (i < total) g_agg[i] = 0.0f;
}
__global__ void k_deg(const int* __restrict__ dst, int E) {
    int e = blockIdx.x * blockDim.x + threadIdx.x;
    if (e < E) atomicAdd(&g_deg[dst[e]], 1.0f);
}

// convert x (fp32) -> fp16 hi/lo split, padded to MPAD rows with zeros
__global__ void k_conv(const float* __restrict__ x0, int layer, int Nn) {
    int i = blockIdx.x * blockDim.x + threadIdx.x;
    if (i >= MPAD * 128) return;
    const float* src = (layer == 0) ? x0 : (const float*)g_x;
    int row = i >> 7;
    float v = (row < Nn) ? src[i] : 0.0f;
    __half h = __float2half_rn(v);
    g_Ah[i] = h;
    g_Al[i] = __float2half_rn(v - __half2float(h));
}

// pack weights transposed: Bmat[n][k]; n<2048 -> W_rel[r=n>>7][d=k][n&127], else W_self
__global__ void k_packb(const float* __restrict__ Wrel, const float* __restrict__ Wself) {
    int idx = blockIdx.x * blockDim.x + threadIdx.x;
    if (idx >= NCOL * 128) return;
    int n = idx >> 7, d = idx & 127;   // d = k index
    float v;
    if (n < 2048) {
        int r = n >> 7, k = n & 127;
        v = Wrel[((size_t)r * 128 + d) * 128 + k];
    } else {
        v = Wself[d * 128 + (n - 2048)];
    }
    __half h = __float2half_rn(v);
    g_Bh[idx] = h;
    g_Bl[idx] = __float2half_rn(v - __half2float(h));
}

// ---------------- mma.sync GEMM: g_trans(MPAD x 2176) = A(MPAD x 128) @ Bmat^T ----------------
// CTA: 128x128 tile, 8 warps (2x4), warp tile 64x32. 3-pass fp16 split, fp32 accum.
#define SA_H 0
#define SA_L 32768
#define SB_H 65536
#define SB_L 98304
#define GSMEM 131072

// load 128x128 fp16 tile to smem: row stride 256B, 16B chunk c swizzled by (c ^ (row&7))
__device__ __forceinline__ void load_tile(char* dstbase, const __half* g, int row0, int t) {
#pragma unroll
    for (int it = 0; it < 8; it++) {
        int cl = it * 256 + t;
        int row = cl >> 4, c = cl & 15;
        uint4 v = *(const uint4*)(g + (size_t)(row0 + row) * 128 + c * 8);
        *(uint4*)(dstbase + row * 256 + ((c ^ (row & 7)) * 16)) = v;
    }
}

__global__ __launch_bounds__(256) void k_gemm() {
    extern __shared__ char smem[];
    int t = threadIdx.x, lane = t & 31, w = t >> 5;
    int n0 = blockIdx.x * 128, m0 = blockIdx.y * 128;

    load_tile(smem + SA_H, g_Ah, m0, t);
    load_tile(smem + SA_L, g_Al, m0, t);
    load_tile(smem + SB_H, g_Bh, n0, t);
    load_tile(smem + SB_L, g_Bl, n0, t);
    __syncthreads();

    int wm = (w & 1) * 64, wn = (w >> 1) * 32;
    float acc[4][4][4];
#pragma unroll
    for (int i = 0; i < 4; i++)
#pragma unroll
        for (int j = 0; j < 4; j++)
#pragma unroll
            for (int q = 0; q < 4; q++) acc[i][j][q] = 0.0f;

    uint32_t sbase = smem_u32(smem);
    // A ldmatrix lane mapping: tile = lane>>3 (0..3), r = lane&7
    int atile = lane >> 3, ar = lane & 7;
    int arow_base = wm + ((atile & 1) << 3) + ar;   // + i*16
    int achunk_sel = atile >> 1;                     // 0: k-lo chunk, 1: k-hi chunk
    // B ldmatrix lane mapping (lanes 0-15 used): half = bit3, r = low3
    int bl = lane & 15;
    int bhalf = bl >> 3, br = bl & 7;

#pragma unroll
    for (int pass = 0; pass < 3; pass++) {
        uint32_t abase = sbase + ((pass == 1) ? SA_L : SA_H);
        uint32_t bbase = sbase + ((pass == 2) ? SB_L : SB_H);
#pragma unroll
        for (int ks = 0; ks < 8; ks++) {
            uint32_t a[4][4];
            uint32_t b[4][2];
            int ac = ks * 2 + achunk_sel;
#pragma unroll
            for (int i = 0; i < 4; i++) {
                int row = arow_base + i * 16;
                uint32_t addr = abase + row * 256 + ((ac ^ (row & 7)) * 16);
                ldm_x4(a[i][0], a[i][1], a[i][2], a[i][3], addr);
            }
            int bc = ks * 2 + bhalf;
#pragma unroll
            for (int j = 0; j < 4; j++) {
                int row = wn + j * 8 + br;
                uint32_t addr = bbase + row * 256 + ((bc ^ (row & 7)) * 16);
                ldm_x2(b[j][0], b[j][1], addr);
            }
#pragma unroll
            for (int i = 0; i < 4; i++)
#pragma unroll
                for (int j = 0; j < 4; j++)
                    mma16816(acc[i][j], a[i][0], a[i][1], a[i][2], a[i][3], b[j][0], b[j][1]);
        }
    }
    __syncthreads();

    // stage C through smem (stride 136 floats), then coalesced global writes
    float* cs = (float*)smem;
#pragma unroll
    for (int i = 0; i < 4; i++) {
#pragma unroll
        for (int j = 0; j < 4; j++) {
            int r = wm + i * 16 + (lane >> 2);
            int c = wn + j * 8 + 2 * (lane & 3);
            *(float2*)(cs + r * 136 + c) = make_float2(acc[i][j][0], acc[i][j][1]);
            *(float2*)(cs + (r + 8) * 136 + c) = make_float2(acc[i][j][2], acc[i][j][3]);
        }
    }
    __syncthreads();
#pragma unroll
    for (int it = 0; it < 16; it++) {
        int idx = it * 256 + t;
        int row = idx >> 5, c4 = (idx & 31) * 4;
        float4 v = *(const float4*)(cs + row * 136 + c4);
        *(float4*)(g_trans + (size_t)(m0 + row) * NCOL + n0 + c4) = v;
    }
}

// ---------------- edge scatter: agg[dst] += trans[src][etype*128 + :] ----------------
__global__ void k_scatter(const int* __restrict__ src, const int* __restrict__ dst,
                          const int* __restrict__ et, int E) {
    int gw = (blockIdx.x * blockDim.x + threadIdx.x) >> 5;
    int lane = threadIdx.x & 31;
    if (gw >= E) return;
    int s = src[gw], dd = dst[gw], r = et[gw];
    float4 v = *(const float4*)(g_trans + (size_t)s * NCOL + r * 128 + lane * 4);
    float* ap = g_agg + (size_t)dd * 128 + lane * 4;
    unsigned long long gp;
    asm volatile("cvta.to.global.u64 %0, %1;" : "=l"(gp) : "l"(ap));
    asm volatile("red.global.add.v4.f32 [%0], {%1, %2, %3, %4};"
                 :: "l"(gp), "f"(v.x), "f"(v.y), "f"(v.z), "f"(v.w) : "memory");
}

// ---------------- node update: relu(self + b + agg/denom) then LayerNorm ----------------
__global__ void k_update(const float* __restrict__ bself, const float* __restrict__ g,
                         const float* __restrict__ b, float* __restrict__ enc_out,
                         int layer, int M) {
    int n = blockIdx.x;
    int d = threadIdx.x;  // 128 threads
    if (n >= M) return;
    float denom = fmaxf(g_deg[n], 1.0f);
    float v = g_trans[(size_t)n * NCOL + 2048 + d] + bself[d] + g_agg[(size_t)n * 128 + d] / denom;
    v = fmaxf(v, 0.0f);

    __shared__ float red1[4], red2[4];
    float s = v;
#pragma unroll
    for (int o = 16; o > 0; o >>= 1) s += __shfl_xor_sync(0xFFFFFFFFu, s, o);
    if ((d & 31) == 0) red1[d >> 5] = s;
    __syncthreads();
    float mu = (red1[0] + red1[1] + red1[2] + red1[3]) * (1.0f / 128.0f);
    float dv = v - mu;
    float q = dv * dv;
#pragma unroll
    for (int o = 16; o > 0; o >>= 1) q += __shfl_xor_sync(0xFFFFFFFFu, q, o);
    if ((d & 31) == 0) red2[d >> 5] = q;
    __syncthreads();
    float var = (red2[0] + red2[1] + red2[2] + red2[3]) * (1.0f / 128.0f);
    float out = dv * rsqrtf(var + 1e-5f) * g[d] + b[d];
    if (layer == 0) g_x[(size_t)n * 128 + d] = out;
    else            enc_out[(size_t)n * 128 + d] = out;
}

// ---------------- build LSTM input sequence ----------------
__global__ void k_seq(const float* __restrict__ enc, const int* __restrict__ pn,
                      const int* __restrict__ pr, const float* __restrict__ rel) {
    int pl = blockIdx.x;          // P*L blocks
    int p = pl >> 2, t = pl & 3;
    int d = threadIdx.x;          // 128
    int node = pn[p * 4 + t];
    float* o = g_seq + ((size_t)p * 4 + t) * 256;
    o[d] = enc[(size_t)node * 128 + d];
    float rv = 0.0f;
    if (t > 0) { int r = pr[p * 3 + (t - 1)]; rv = rel[r * 128 + d]; }
    o[128 + d] = rv;
}

// transpose LSTM weights: WT[dir][d][j]
__global__ void k_wt(const float* __restrict__ Wih_f, const float* __restrict__ Whh_f,
                     const float* __restrict__ Wih_b, const float* __restrict__ Whh_b) {
    int idx = blockIdx.x * blockDim.x + threadIdx.x;
    if (idx >= 2 * 384 * 512) return;
    int dir = idx / (384 * 512);
    int rem = idx % (384 * 512);
    int d = rem / 512, j = rem % 512;
    const float* Wih = dir ? Wih_b : Wih_f;
    const float* Whh = dir ? Whh_b : Whh_f;
    float v = (d < 256) ? Wih[j * 256 + d] : Whh[j * 128 + (d - 256)];
    g_WT[dir][rem] = v;
}

// ---------------- bidirectional LSTM (8 paths per block) ----------------
__global__ __launch_bounds__(512) void k_lstm(const float* __restrict__ bf,
                                              const float* __restrict__ bb) {
    const int PB = 8;
    __shared__ float xt[PB][256];
    __shared__ float hs[PB][128];
    __shared__ float cs[PB][128];
    __shared__ float gs[PB][512];
    int dir = blockIdx.y;
    const float* WT = g_WT[dir];
    const float* bias = dir ? bb : bf;
    int p0 = blockIdx.x * PB;
    int t = threadIdx.x;   // 512 threads; thread t owns gate column t

    for (int i = t; i < PB * 128; i += 512) { ((float*)hs)[i] = 0.0f; ((float*)cs)[i] = 0.0f; }
    float bj = bias[t];
    __syncthreads();

    for (int step = 0; step < 4; step++) {
        int tt = dir ? (3 - step) : step;
        for (int i = t; i < PB * 256; i += 512) {
            int pp = i >> 8, d = i & 255;
            xt[pp][d] = g_seq[((size_t)(p0 + pp) * 4 + tt) * 256 + d];
        }
        __syncthreads();
        float acc[PB];
#pragma unroll
        for (int p = 0; p < PB; p++) acc[p] = bj;
        for (int d = 0; d < 256; d++) {
            float w = WT[d * 512 + t];
#pragma unroll
            for (int p = 0; p < PB; p++) acc[p] = fmaf(w, xt[p][d], acc[p]);
        }
        for (int d = 0; d < 128; d++) {
            float w = WT[(256 + d) * 512 + t];
#pragma unroll
            for (int p = 0; p < PB; p++) acc[p] = fmaf(w, hs[p][d], acc[p]);
        }
#pragma unroll
        for (int p = 0; p < PB; p++) gs[p][t] = acc[p];
        __syncthreads();
        for (int i = t; i < PB * 128; i += 512) {
            int pp = i >> 7, k = i & 127;
            float ig = 1.0f / (1.0f + expf(-gs[pp][k]));
            float fg = 1.0f / (1.0f + expf(-gs[pp][128 + k]));
            float gg = tanhf(gs[pp][256 + k]);
            float og = 1.0f / (1.0f + expf(-gs[pp][384 + k]));
            float c = fg * cs[pp][k] + ig * gg;
            cs[pp][k] = c;
            hs[pp][k] = og * tanhf(c);
        }
        __syncthreads();
    }
    for (int i = t; i < PB * 128; i += 512) {
        int pp = i >> 7, k = i & 127;
        g_h[((size_t)dir * 256 + p0 + pp) * 128 + k] = hs[pp][k];
    }
}

// ---------------- output head ----------------
__global__ void k_head(const float* __restrict__ Wop, const float* __restrict__ bop,
                       const float* __restrict__ q, const float* __restrict__ Ws1,
                       const float* __restrict__ bs1, const float* __restrict__ Ws2,
                       const float* __restrict__ bs2,
                       float* __restrict__ pe_out, float* __restrict__ sim_out) {
    int p = blockIdx.x;
    int k = threadIdx.x;   // 128
    __shared__ float cat[256];
    __shared__ float cat2[256];
    __shared__ float red[4];
    cat[k]       = g_h[(size_t)p * 128 + k];
    cat[128 + k] = g_h[(size_t)(256 + p) * 128 + k];
    __syncthreads();
    float acc = bop[k];
    for (int j = 0; j < 256; j++) acc = fmaf(cat[j], Wop[k * 256 + j], acc);
    float pe = fmaxf(acc, 0.0f);
    pe_out[(size_t)p * 128 + k] = pe;
    cat2[k] = pe;
    cat2[128 + k] = q[k];
    __syncthreads();
    float a2 = bs1[k];
    for (int j = 0; j < 256; j++) a2 = fmaf(cat2[j], Ws1[k * 256 + j], a2);
    float hdn = fmaxf(a2, 0.0f);
    float s = hdn * Ws2[k];
#pragma unroll
    for (int o = 16; o > 0; o >>= 1) s += __shfl_xor_sync(0xFFFFFFFFu, s, o);
    if ((k & 31) == 0) red[k >> 5] = s;
    __syncthreads();
    if (k == 0) {
        float tot = red[0] + red[1] + red[2] + red[3] + bs2[0];
        sim_out[p] = 1.0f / (1.0f + expf(-tot));
    }
}

// ---------------- launch ----------------
extern "C" void kernel_launch(void* const* d_in, const int* in_sizes, int n_in,
                              void* d_out, int out_size) {
    const float* node_features = (const float*)d_in[0];
    const int*   edge_index    = (const int*)d_in[1];
    const int*   edge_types    = (const int*)d_in[2];
    const float* query         = (const float*)d_in[3];
    const int*   path_nodes    = (const int*)d_in[4];
    const int*   path_rel      = (const int*)d_in[5];
    const float* W_self        = (const float*)d_in[6];
    const float* b_self        = (const float*)d_in[7];
    const float* W_rel         = (const float*)d_in[8];
    const float* ln_g          = (const float*)d_in[9];
    const float* ln_b          = (const float*)d_in[10];
    const float* rel_emb       = (const float*)d_in[11];
    const float* W_ih_f        = (const float*)d_in[12];
    const float* W_hh_f        = (const float*)d_in[13];
    const float* b_f           = (const float*)d_in[14];
    const float* W_ih_b        = (const float*)d_in[15];
    const float* W_hh_b        = (const float*)d_in[16];
    const float* b_b           = (const float*)d_in[17];
    const float* W_op          = (const float*)d_in[18];
    const float* b_op          = (const float*)d_in[19];
    const float* W_s1          = (const float*)d_in[20];
    const float* b_s1          = (const float*)d_in[21];
    const float* W_s2          = (const float*)d_in[22];
    const float* b_s2          = (const float*)d_in[23];
    (void)n_in; (void)out_size;

    const int N = in_sizes[0] / 128;   // 50000
    const int E = in_sizes[1] / 2;     // 800000
    const int P = in_sizes[4] / 4;     // 256

    float* out     = (float*)d_out;
    float* enc_out = out;
    float* pe_out  = out + (size_t)N * 128;
    float* sim_out = pe_out + (size_t)P * 128;

    const int* src = edge_index;
    const int* dst = edge_index + E;

    cudaFuncSetAttribute(k_gemm, cudaFuncAttributeMaxDynamicSharedMemorySize, GSMEM);

    k_zero_deg<<<(N + 255) / 256, 256>>>(N);
    k_deg<<<(E + 255) / 256, 256>>>(dst, E);

    for (int l = 0; l < 2; l++) {
        k_conv<<<(MPAD * 128 + 255) / 256, 256>>>(node_features, l, N);
        k_packb<<<(NCOL * 128 + 255) / 256, 256>>>(W_rel + (size_t)l * R * 128 * 128,
                                                   W_self + (size_t)l * 128 * 128);
        dim3 ggrid(NCOL / 128, MPAD / 128);
        k_gemm<<<ggrid, 256, GSMEM>>>();
        k_zero_agg<<<(N * 128 + 255) / 256, 256>>>(N * 128);
        k_scatter<<<(E + 7) / 8, 256>>>(src, dst, edge_types, E);
        k_update<<<N, 128>>>(b_self + l * 128, ln_g + l * 128, ln_b + l * 128,
                             enc_out, l, N);
    }

    k_seq<<<P * 4, 128>>>(enc_out, path_nodes, path_rel, rel_emb);
    k_wt<<<(2 * 384 * 512 + 255) / 256, 256>>>(W_ih_f, W_hh_f, W_ih_b, W_hh_b);
    k_lstm<<<dim3(P / 8, 2), 512>>>(b_f, b_b);
    k_head<<<P, 128>>>(W_op, b_op, query, W_s1, b_s1, W_s2, b_s2, pe_out, sim_out);
}

// round 5
// speedup vs baseline: 1.8939x; 1.1260x over previous
#include <cuda_runtime.h>
#include <cuda_fp16.h>
#include <math.h>
#include <stdint.h>

#define D 128
#define R 16
#define NCOL 2176          // R*D + D
#define MPAD 50048         // 391 * 128

// ---------------- scratch (device globals; allocation-free) ----------------
__device__ __half g_trans16[(size_t)MPAD * 2048];  // 204 MB, relation messages
__device__ float g_self[(size_t)MPAD * 128];       // self-transform block (fp32)
__device__ float g_agg[(size_t)MPAD * 128];
__device__ float g_x[(size_t)MPAD * 128];
__device__ float g_deg[50000];
__device__ __half g_Ah[(size_t)MPAD * 128];
__device__ __half g_Al[(size_t)MPAD * 128];
__device__ __half g_Bh[NCOL * 128];                 // [n][k]
__device__ __half g_Bl[NCOL * 128];
__device__ float g_seq[256 * 4 * 256];
__device__ float g_WT[2][384 * 512];
__device__ float g_h[2 * 256 * 128];

// ---------------- bit-cast helpers ----------------
__device__ __forceinline__ uint32_t h2_as_u32(__half2 h) {
    uint32_t u; *(__half2*)&u = h; return u;
}
__device__ __forceinline__ __half2 u32_as_h2(uint32_t u) {
    __half2 h; *(uint32_t*)&h = u; return h;
}

// ---------------- PTX helpers ----------------
__device__ __forceinline__ uint32_t smem_u32(const void* p) {
    return (uint32_t)__cvta_generic_to_shared(p);
}
__device__ __forceinline__ void ldm_x4(uint32_t& r0, uint32_t& r1, uint32_t& r2, uint32_t& r3,
                                       uint32_t a) {
    asm volatile("ldmatrix.sync.aligned.m8n8.x4.shared.b16 {%0,%1,%2,%3}, [%4];"
                 : "=r"(r0), "=r"(r1), "=r"(r2), "=r"(r3) : "r"(a));
}
__device__ __forceinline__ void ldm_x2(uint32_t& r0, uint32_t& r1, uint32_t a) {
    asm volatile("ldmatrix.sync.aligned.m8n8.x2.shared.b16 {%0,%1}, [%2];"
                 : "=r"(r0), "=r"(r1) : "r"(a));
}
__device__ __forceinline__ void mma16816(float* c, uint32_t a0, uint32_t a1, uint32_t a2,
                                         uint32_t a3, uint32_t b0, uint32_t b1) {
    asm volatile(
        "mma.sync.aligned.m16n8k16.row.col.f32.f16.f16.f32 "
        "{%0,%1,%2,%3}, {%4,%5,%6,%7}, {%8,%9}, {%0,%1,%2,%3};"
        : "+f"(c[0]), "+f"(c[1]), "+f"(c[2]), "+f"(c[3])
        : "r"(a0), "r"(a1), "r"(a2), "r"(a3), "r"(b0), "r"(b1));
}

// ---------------- small utility kernels ----------------
__global__ void k_zero_deg(int N) {
    int i = blockIdx.x * blockDim.x + threadIdx.x;
    if (i < N) g_deg[i] = 0.0f;
}
__global__ void k_zero_agg(int total) {
    int i = blockIdx.x * blockDim.x + threadIdx.x;
    if (i < total) g_agg[i] = 0.0f;
}
__global__ void k_deg(const int* __restrict__ dst, int E) {
    int e = blockIdx.x * blockDim.x + threadIdx.x;
    if (e < E) atomicAdd(&g_deg[dst[e]], 1.0f);
}

// convert x (fp32) -> fp16 hi/lo split, padded to MPAD rows with zeros
__global__ void k_conv(const float* __restrict__ x0, int layer, int Nn) {
    int i4 = blockIdx.x * blockDim.x + threadIdx.x;   // float4 index
    if (i4 >= MPAD * 32) return;
    const float* src = (layer == 0) ? x0 : (const float*)g_x;
    int row = i4 >> 5;
    float4 v = make_float4(0.f, 0.f, 0.f, 0.f);
    if (row < Nn) v = *(const float4*)(src + (size_t)i4 * 4);
    __half2 h0 = __floats2half2_rn(v.x, v.y);
    __half2 h1 = __floats2half2_rn(v.z, v.w);
    float2 f0 = __half22float2(h0), f1 = __half22float2(h1);
    __half2 l0 = __floats2half2_rn(v.x - f0.x, v.y - f0.y);
    __half2 l1 = __floats2half2_rn(v.z - f1.x, v.w - f1.y);
    ((uint2*)g_Ah)[i4] = make_uint2(h2_as_u32(h0), h2_as_u32(h1));
    ((uint2*)g_Al)[i4] = make_uint2(h2_as_u32(l0), h2_as_u32(l1));
}

// pack weights transposed: Bmat[n][k]
__global__ void k_packb(const float* __restrict__ Wrel, const float* __restrict__ Wself) {
    int idx = blockIdx.x * blockDim.x + threadIdx.x;
    if (idx >= NCOL * 128) return;
    int n = idx >> 7, d = idx & 127;   // d = k index
    float v;
    if (n < 2048) {
        int r = n >> 7, k = n & 127;
        v = Wrel[((size_t)r * 128 + d) * 128 + k];
    } else {
        v = Wself[d * 128 + (n - 2048)];
    }
    __half h = __float2half_rn(v);
    g_Bh[idx] = h;
    g_Bl[idx] = __float2half_rn(v - __half2float(h));
}

// ---------------- mma.sync GEMM ----------------
// CTA: 128x128 tile, 8 warps (2x4), warp tile 64x32. 3-pass fp16 split, fp32 accum.
// Column blocks 0..15 -> g_trans16 (fp16); block 16 (self) -> g_self (fp32).
#define SA_H 0
#define SA_L 32768
#define SB_H 65536
#define SB_L 98304
#define GSMEM 131072

__device__ __forceinline__ void load_tile(char* dstbase, const __half* g, int row0, int t) {
#pragma unroll
    for (int it = 0; it < 8; it++) {
        int cl = it * 256 + t;
        int row = cl >> 4, c = cl & 15;
        uint4 v = *(const uint4*)(g + (size_t)(row0 + row) * 128 + c * 8);
        *(uint4*)(dstbase + row * 256 + ((c ^ (row & 7)) * 16)) = v;
    }
}

__global__ __launch_bounds__(256) void k_gemm() {
    extern __shared__ char smem[];
    int t = threadIdx.x, lane = t & 31, w = t >> 5;
    int bx = blockIdx.x;
    int n0 = bx * 128, m0 = blockIdx.y * 128;

    load_tile(smem + SA_H, g_Ah, m0, t);
    load_tile(smem + SA_L, g_Al, m0, t);
    load_tile(smem + SB_H, g_Bh, n0, t);
    load_tile(smem + SB_L, g_Bl, n0, t);
    __syncthreads();

    int wm = (w & 1) * 64, wn = (w >> 1) * 32;
    float acc[4][4][4];
#pragma unroll
    for (int i = 0; i < 4; i++)
#pragma unroll
        for (int j = 0; j < 4; j++)
#pragma unroll
            for (int q = 0; q < 4; q++) acc[i][j][q] = 0.0f;

    uint32_t sbase = smem_u32(smem);
    int atile = lane >> 3, ar = lane & 7;
    int arow_base = wm + ((atile & 1) << 3) + ar;
    int achunk_sel = atile >> 1;
    int bl = lane & 15;
    int bhalf = bl >> 3, br = bl & 7;

#pragma unroll
    for (int pass = 0; pass < 3; pass++) {
        uint32_t abase = sbase + ((pass == 1) ? SA_L : SA_H);
        uint32_t bbase = sbase + ((pass == 2) ? SB_L : SB_H);
#pragma unroll
        for (int ks = 0; ks < 8; ks++) {
            uint32_t a[4][4];
            uint32_t b[4][2];
            int ac = ks * 2 + achunk_sel;
#pragma unroll
            for (int i = 0; i < 4; i++) {
                int row = arow_base + i * 16;
                uint32_t addr = abase + row * 256 + ((ac ^ (row & 7)) * 16);
                ldm_x4(a[i][0], a[i][1], a[i][2], a[i][3], addr);
            }
            int bc = ks * 2 + bhalf;
#pragma unroll
            for (int j = 0; j < 4; j++) {
                int row = wn + j * 8 + br;
                uint32_t addr = bbase + row * 256 + ((bc ^ (row & 7)) * 16);
                ldm_x2(b[j][0], b[j][1], addr);
            }
#pragma unroll
            for (int i = 0; i < 4; i++)
#pragma unroll
                for (int j = 0; j < 4; j++)
                    mma16816(acc[i][j], a[i][0], a[i][1], a[i][2], a[i][3], b[j][0], b[j][1]);
        }
    }
    __syncthreads();

    if (bx < 16) {
        // fp16 output: stage halves in smem (row stride 136 halves = 272B), then coalesced
        __half* cs = (__half*)smem;
#pragma unroll
        for (int i = 0; i < 4; i++) {
#pragma unroll
            for (int j = 0; j < 4; j++) {
                int r = wm + i * 16 + (lane >> 2);
                int c = wn + j * 8 + 2 * (lane & 3);
                *(__half2*)(cs + r * 136 + c) = __floats2half2_rn(acc[i][j][0], acc[i][j][1]);
                *(__half2*)(cs + (r + 8) * 136 + c) = __floats2half2_rn(acc[i][j][2], acc[i][j][3]);
            }
        }
        __syncthreads();
#pragma unroll
        for (int it = 0; it < 8; it++) {
            int idx = it * 256 + t;              // 2048 chunks: 128 rows x 16 x 16B
            int row = idx >> 4, ch = idx & 15;
            uint4 v = *(const uint4*)(cs + row * 136 + ch * 8);
            *(uint4*)(g_trans16 + (size_t)(m0 + row) * 2048 + n0 + ch * 8) = v;
        }
    } else {
        // self block: fp32 output to g_self
        float* cs = (float*)smem;
#pragma unroll
        for (int i = 0; i < 4; i++) {
#pragma unroll
            for (int j = 0; j < 4; j++) {
                int r = wm + i * 16 + (lane >> 2);
                int c = wn + j * 8 + 2 * (lane & 3);
                *(float2*)(cs + r * 136 + c) = make_float2(acc[i][j][0], acc[i][j][1]);
                *(float2*)(cs + (r + 8) * 136 + c) = make_float2(acc[i][j][2], acc[i][j][3]);
            }
        }
        __syncthreads();
#pragma unroll
        for (int it = 0; it < 16; it++) {
            int idx = it * 256 + t;              // 4096 chunks: 128 rows x 32 x 16B
            int row = idx >> 5, c4 = (idx & 31) * 4;
            float4 v = *(const float4*)(cs + row * 136 + c4);
            *(float4*)(g_self + (size_t)(m0 + row) * 128 + c4) = v;
        }
    }
}

// ---------------- edge scatter: agg[dst] += trans16[src][etype*128 + :] ----------------
// half-warp (16 lanes) per edge: 256B coalesced read, fp32 red.add accumulate
__global__ void k_scatter(const int* __restrict__ src, const int* __restrict__ dst,
                          const int* __restrict__ et, int E) {
    int he = (blockIdx.x * blockDim.x + threadIdx.x) >> 4;
    int lane = threadIdx.x & 15;
    if (he >= E) return;
    int s = src[he], dd = dst[he], r = et[he];
    uint4 raw = *(const uint4*)(g_trans16 + (size_t)s * 2048 + r * 128 + lane * 8);
    float2 f0 = __half22float2(u32_as_h2(raw.x));
    float2 f1 = __half22float2(u32_as_h2(raw.y));
    float2 f2 = __half22float2(u32_as_h2(raw.z));
    float2 f3 = __half22float2(u32_as_h2(raw.w));
    float* ap = g_agg + (size_t)dd * 128 + lane * 8;
    unsigned long long gp;
    asm volatile("cvta.to.global.u64 %0, %1;" : "=l"(gp) : "l"(ap));
    asm volatile("red.global.add.v4.f32 [%0], {%1, %2, %3, %4};"
                 :: "l"(gp), "f"(f0.x), "f"(f0.y), "f"(f1.x), "f"(f1.y) : "memory");
    asm volatile("red.global.add.v4.f32 [%0], {%1, %2, %3, %4};"
                 :: "l"(gp + 16), "f"(f2.x), "f"(f2.y), "f"(f3.x), "f"(f3.y) : "memory");
}

// ---------------- node update: relu(self + b + agg/denom) then LayerNorm ----------------
__global__ void k_update(const float* __restrict__ bself, const float* __restrict__ g,
                         const float* __restrict__ b, float* __restrict__ enc_out,
                         int layer, int M) {
    int n = blockIdx.x;
    int d = threadIdx.x;  // 128 threads
    if (n >= M) return;
    float denom = fmaxf(g_deg[n], 1.0f);
    float v = g_self[(size_t)n * 128 + d] + bself[d] + g_agg[(size_t)n * 128 + d] / denom;
    v = fmaxf(v, 0.0f);

    __shared__ float red1[4], red2[4];
    float s = v;
#pragma unroll
    for (int o = 16; o > 0; o >>= 1) s += __shfl_xor_sync(0xFFFFFFFFu, s, o);
    if ((d & 31) == 0) red1[d >> 5] = s;
    __syncthreads();
    float mu = (red1[0] + red1[1] + red1[2] + red1[3]) * (1.0f / 128.0f);
    float dv = v - mu;
    float q = dv * dv;
#pragma unroll
    for (int o = 16; o > 0; o >>= 1) q += __shfl_xor_sync(0xFFFFFFFFu, q, o);
    if ((d & 31) == 0) red2[d >> 5] = q;
    __syncthreads();
    float var = (red2[0] + red2[1] + red2[2] + red2[3]) * (1.0f / 128.0f);
    float out = dv * rsqrtf(var + 1e-5f) * g[d] + b[d];
    if (layer == 0) g_x[(size_t)n * 128 + d] = out;
    else            enc_out[(size_t)n * 128 + d] = out;
}

// ---------------- build LSTM input sequence ----------------
__global__ void k_seq(const float* __restrict__ enc, const int* __restrict__ pn,
                      const int* __restrict__ pr, const float* __restrict__ rel) {
    int pl = blockIdx.x;          // P*L blocks
    int p = pl >> 2, t = pl & 3;
    int d = threadIdx.x;          // 128
    int node = pn[p * 4 + t];
    float* o = g_seq + ((size_t)p * 4 + t) * 256;
    o[d] = enc[(size_t)node * 128 + d];
    float rv = 0.0f;
    if (t > 0) { int r = pr[p * 3 + (t - 1)]; rv = rel[r * 128 + d]; }
    o[128 + d] = rv;
}

// transpose LSTM weights: WT[dir][d][j]
__global__ void k_wt(const float* __restrict__ Wih_f, const float* __restrict__ Whh_f,
                     const float* __restrict__ Wih_b, const float* __restrict__ Whh_b) {
    int idx = blockIdx.x * blockDim.x + threadIdx.x;
    if (idx >= 2 * 384 * 512) return;
    int dir = idx / (384 * 512);
    int rem = idx % (384 * 512);
    int d = rem / 512, j = rem % 512;
    const float* Wih = dir ? Wih_b : Wih_f;
    const float* Whh = dir ? Whh_b : Whh_f;
    float v = (d < 256) ? Wih[j * 256 + d] : Whh[j * 128 + (d - 256)];
    g_WT[dir][rem] = v;
}

// ---------------- bidirectional LSTM (8 paths per block) ----------------
__global__ __launch_bounds__(512) void k_lstm(const float* __restrict__ bf,
                                              const float* __restrict__ bb) {
    const int PB = 8;
    __shared__ float xt[PB][256];
    __shared__ float hs[PB][128];
    __shared__ float cs[PB][128];
    __shared__ float gs[PB][512];
    int dir = blockIdx.y;
    const float* WT = g_WT[dir];
    const float* bias = dir ? bb : bf;
    int p0 = blockIdx.x * PB;
    int t = threadIdx.x;   // 512 threads; thread t owns gate column t

    for (int i = t; i < PB * 128; i += 512) { ((float*)hs)[i] = 0.0f; ((float*)cs)[i] = 0.0f; }
    float bj = bias[t];
    __syncthreads();

    for (int step = 0; step < 4; step++) {
        int tt = dir ? (3 - step) : step;
        for (int i = t; i < PB * 256; i += 512) {
            int pp = i >> 8, d = i & 255;
            xt[pp][d] = g_seq[((size_t)(p0 + pp) * 4 + tt) * 256 + d];
        }
        __syncthreads();
        float acc[PB];
#pragma unroll
        for (int p = 0; p < PB; p++) acc[p] = bj;
        for (int d = 0; d < 256; d++) {
            float w = WT[d * 512 + t];
#pragma unroll
            for (int p = 0; p < PB; p++) acc[p] = fmaf(w, xt[p][d], acc[p]);
        }
        for (int d = 0; d < 128; d++) {
            float w = WT[(256 + d) * 512 + t];
#pragma unroll
            for (int p = 0; p < PB; p++) acc[p] = fmaf(w, hs[p][d], acc[p]);
        }
#pragma unroll
        for (int p = 0; p < PB; p++) gs[p][t] = acc[p];
        __syncthreads();
        for (int i = t; i < PB * 128; i += 512) {
            int pp = i >> 7, k = i & 127;
            float ig = 1.0f / (1.0f + expf(-gs[pp][k]));
            float fg = 1.0f / (1.0f + expf(-gs[pp][128 + k]));
            float gg = tanhf(gs[pp][256 + k]);
            float og = 1.0f / (1.0f + expf(-gs[pp][384 + k]));
            float c = fg * cs[pp][k] + ig * gg;
            cs[pp][k] = c;
            hs[pp][k] = og * tanhf(c);
        }
        __syncthreads();
    }
    for (int i = t; i < PB * 128; i += 512) {
        int pp = i >> 7, k = i & 127;
        g_h[((size_t)dir * 256 + p0 + pp) * 128 + k] = hs[pp][k];
    }
}

// ---------------- output head ----------------
__global__ void k_head(const float* __restrict__ Wop, const float* __restrict__ bop,
                       const float* __restrict__ q, const float* __restrict__ Ws1,
                       const float* __restrict__ bs1, const float* __restrict__ Ws2,
                       const float* __restrict__ bs2,
                       float* __restrict__ pe_out, float* __restrict__ sim_out) {
    int p = blockIdx.x;
    int k = threadIdx.x;   // 128
    __shared__ float cat[256];
    __shared__ float cat2[256];
    __shared__ float red[4];
    cat[k]       = g_h[(size_t)p * 128 + k];
    cat[128 + k] = g_h[(size_t)(256 + p) * 128 + k];
    __syncthreads();
    float acc = bop[k];
    for (int j = 0; j < 256; j++) acc = fmaf(cat[j], Wop[k * 256 + j], acc);
    float pe = fmaxf(acc, 0.0f);
    pe_out[(size_t)p * 128 + k] = pe;
    cat2[k] = pe;
    cat2[128 + k] = q[k];
    __syncthreads();
    float a2 = bs1[k];
    for (int j = 0; j < 256; j++) a2 = fmaf(cat2[j], Ws1[k * 256 + j], a2);
    float hdn = fmaxf(a2, 0.0f);
    float s = hdn * Ws2[k];
#pragma unroll
    for (int o = 16; o > 0; o >>= 1) s += __shfl_xor_sync(0xFFFFFFFFu, s, o);
    if ((k & 31) == 0) red[k >> 5] = s;
    __syncthreads();
    if (k == 0) {
        float tot = red[0] + red[1] + red[2] + red[3] + bs2[0];
        sim_out[p] = 1.0f / (1.0f + expf(-tot));
    }
}

// ---------------- launch ----------------
extern "C" void kernel_launch(void* const* d_in, const int* in_sizes, int n_in,
                              void* d_out, int out_size) {
    const float* node_features = (const float*)d_in[0];
    const int*   edge_index    = (const int*)d_in[1];
    const int*   edge_types    = (const int*)d_in[2];
    const float* query         = (const float*)d_in[3];
    const int*   path_nodes    = (const int*)d_in[4];
    const int*   path_rel      = (const int*)d_in[5];
    const float* W_self        = (const float*)d_in[6];
    const float* b_self        = (const float*)d_in[7];
    const float* W_rel         = (const float*)d_in[8];
    const float* ln_g          = (const float*)d_in[9];
    const float* ln_b          = (const float*)d_in[10];
    const float* rel_emb       = (const float*)d_in[11];
    const float* W_ih_f        = (const float*)d_in[12];
    const float* W_hh_f        = (const float*)d_in[13];
    const float* b_f           = (const float*)d_in[14];
    const float* W_ih_b        = (const float*)d_in[15];
    const float* W_hh_b        = (const float*)d_in[16];
    const float* b_b           = (const float*)d_in[17];
    const float* W_op          = (const float*)d_in[18];
    const float* b_op          = (const float*)d_in[19];
    const float* W_s1          = (const float*)d_in[20];
    const float* b_s1          = (const float*)d_in[21];
    const float* W_s2          = (const float*)d_in[22];
    const float* b_s2          = (const float*)d_in[23];
    (void)n_in; (void)out_size;

    const int N = in_sizes[0] / 128;   // 50000
    const int E = in_sizes[1] / 2;     // 800000
    const int P = in_sizes[4] / 4;     // 256

    float* out     = (float*)d_out;
    float* enc_out = out;
    float* pe_out  = out + (size_t)N * 128;
    float* sim_out = pe_out + (size_t)P * 128;

    const int* src = edge_index;
    const int* dst = edge_index + E;

    cudaFuncSetAttribute(k_gemm, cudaFuncAttributeMaxDynamicSharedMemorySize, GSMEM);

    k_zero_deg<<<(N + 255) / 256, 256>>>(N);
    k_deg<<<(E + 255) / 256, 256>>>(dst, E);

    for (int l = 0; l < 2; l++) {
        k_conv<<<(MPAD * 32 + 255) / 256, 256>>>(node_features, l, N);
        k_packb<<<(NCOL * 128 + 255) / 256, 256>>>(W_rel + (size_t)l * R * 128 * 128,
                                                   W_self + (size_t)l * 128 * 128);
        dim3 ggrid(NCOL / 128, MPAD / 128);
        k_gemm<<<ggrid, 256, GSMEM>>>();
        k_zero_agg<<<(N * 128 + 255) / 256, 256>>>(N * 128);
        k_scatter<<<(E + 15) / 16, 256>>>(src, dst, edge_types, E);
        k_update<<<N, 128>>>(b_self + l * 128, ln_g + l * 128, ln_b + l * 128,
                             enc_out, l, N);
    }

    k_seq<<<P * 4, 128>>>(enc_out, path_nodes, path_rel, rel_emb);
    k_wt<<<(2 * 384 * 512 + 255) / 256, 256>>>(W_ih_f, W_hh_f, W_ih_b, W_hh_b);
    k_lstm<<<dim3(P / 8, 2), 512>>>(b_f, b_b);
    k_head<<<P, 128>>>(W_op, b_op, query, W_s1, b_s1, W_s2, b_s2, pe_out, sim_out);
}

// round 6
// speedup vs baseline: 2.0537x; 1.0844x over previous
#include <cuda_runtime.h>
#include <cuda_fp16.h>
#include <math.h>
#include <stdint.h>

#define D 128
#define R 16
#define NCOL 2176          // R*D + D
#define MPAD 50048         // 391 * 128
#define NMAX 50000
#define EMAX 800000

// ---------------- scratch (device globals; allocation-free) ----------------
__device__ __half g_trans16[(size_t)MPAD * 2048];  // 204 MB, relation messages
__device__ float g_self[(size_t)MPAD * 128];       // self-transform block (fp32)
__device__ float g_x[(size_t)MPAD * 128];
__device__ __half g_Ah[(size_t)MPAD * 128];
__device__ __half g_Al[(size_t)MPAD * 128];
__device__ __half g_Bh[NCOL * 128];                 // [n][k]
__device__ __half g_Bl[NCOL * 128];
__device__ float g_seq[256 * 4 * 256];
__device__ float g_WT[2][384 * 512];
__device__ float g_h[2 * 256 * 128];
// CSR
__device__ int g_cnt[NMAX];
__device__ int g_off[NMAX + 1];
__device__ int g_cur[NMAX];
__device__ uint32_t g_sed[EMAX];   // packed src | (r<<16)

// ---------------- bit-cast helpers ----------------
__device__ __forceinline__ uint32_t h2_as_u32(__half2 h) {
    uint32_t u; *(__half2*)&u = h; return u;
}
__device__ __forceinline__ __half2 u32_as_h2(uint32_t u) {
    __half2 h; *(uint32_t*)&h = u; return h;
}

// ---------------- PTX helpers ----------------
__device__ __forceinline__ uint32_t smem_u32(const void* p) {
    return (uint32_t)__cvta_generic_to_shared(p);
}
__device__ __forceinline__ void ldm_x4(uint32_t& r0, uint32_t& r1, uint32_t& r2, uint32_t& r3,
                                       uint32_t a) {
    asm volatile("ldmatrix.sync.aligned.m8n8.x4.shared.b16 {%0,%1,%2,%3}, [%4];"
                 : "=r"(r0), "=r"(r1), "=r"(r2), "=r"(r3) : "r"(a));
}
__device__ __forceinline__ void ldm_x2(uint32_t& r0, uint32_t& r1, uint32_t a) {
    asm volatile("ldmatrix.sync.aligned.m8n8.x2.shared.b16 {%0,%1}, [%2];"
                 : "=r"(r0), "=r"(r1) : "r"(a));
}
__device__ __forceinline__ void mma16816(float* c, uint32_t a0, uint32_t a1, uint32_t a2,
                                         uint32_t a3, uint32_t b0, uint32_t b1) {
    asm volatile(
        "mma.sync.aligned.m16n8k16.row.col.f32.f16.f16.f32 "
        "{%0,%1,%2,%3}, {%4,%5,%6,%7}, {%8,%9}, {%0,%1,%2,%3};"
        : "+f"(c[0]), "+f"(c[1]), "+f"(c[2]), "+f"(c[3])
        : "r"(a0), "r"(a1), "r"(a2), "r"(a3), "r"(b0), "r"(b1));
}

// ---------------- CSR build ----------------
__global__ void k_zero_cnt(int N) {
    int i = blockIdx.x * blockDim.x + threadIdx.x;
    if (i < N) g_cnt[i] = 0;
}
__global__ void k_hist(const int* __restrict__ dst, int E) {
    int e = blockIdx.x * blockDim.x + threadIdx.x;
    if (e < E) atomicAdd(&g_cnt[dst[e]], 1);
}
__global__ __launch_bounds__(1024) void k_scan(int N) {
    __shared__ int sh[1024];
    int t = threadIdx.x;
    int chunk = (N + 1023) / 1024;
    int c0 = t * chunk, c1 = min(c0 + chunk, N);
    int s = 0;
    for (int i = c0; i < c1; i++) s += g_cnt[i];
    sh[t] = s;
    __syncthreads();
    for (int o = 1; o < 1024; o <<= 1) {
        int v = (t >= o) ? sh[t - o] : 0;
        __syncthreads();
        sh[t] += v;
        __syncthreads();
    }
    int run = sh[t] - s;   // exclusive prefix for this chunk
    for (int i = c0; i < c1; i++) {
        g_off[i] = run;
        g_cur[i] = run;
        run += g_cnt[i];
    }
    if (t == 1023) g_off[N] = run;
}
__global__ void k_place(const int* __restrict__ src, const int* __restrict__ dst,
                        const int* __restrict__ et, int E) {
    int e = blockIdx.x * blockDim.x + threadIdx.x;
    if (e >= E) return;
    int pos = atomicAdd(&g_cur[dst[e]], 1);
    g_sed[pos] = (uint32_t)src[e] | ((uint32_t)et[e] << 16);
}

// ---------------- small utility kernels ----------------
// convert x (fp32) -> fp16 hi/lo split, padded to MPAD rows with zeros
__global__ void k_conv(const float* __restrict__ x0, int layer, int Nn) {
    int i4 = blockIdx.x * blockDim.x + threadIdx.x;   // float4 index
    if (i4 >= MPAD * 32) return;
    const float* src = (layer == 0) ? x0 : (const float*)g_x;
    int row = i4 >> 5;
    float4 v = make_float4(0.f, 0.f, 0.f, 0.f);
    if (row < Nn) v = *(const float4*)(src + (size_t)i4 * 4);
    __half2 h0 = __floats2half2_rn(v.x, v.y);
    __half2 h1 = __floats2half2_rn(v.z, v.w);
    float2 f0 = __half22float2(h0), f1 = __half22float2(h1);
    __half2 l0 = __floats2half2_rn(v.x - f0.x, v.y - f0.y);
    __half2 l1 = __floats2half2_rn(v.z - f1.x, v.w - f1.y);
    ((uint2*)g_Ah)[i4] = make_uint2(h2_as_u32(h0), h2_as_u32(h1));
    ((uint2*)g_Al)[i4] = make_uint2(h2_as_u32(l0), h2_as_u32(l1));
}

// pack weights transposed: Bmat[n][k]
__global__ void k_packb(const float* __restrict__ Wrel, const float* __restrict__ Wself) {
    int idx = blockIdx.x * blockDim.x + threadIdx.x;
    if (idx >= NCOL * 128) return;
    int n = idx >> 7, d = idx & 127;   // d = k index
    float v;
    if (n < 2048) {
        int r = n >> 7, k = n & 127;
        v = Wrel[((size_t)r * 128 + d) * 128 + k];
    } else {
        v = Wself[d * 128 + (n - 2048)];
    }
    __half h = __float2half_rn(v);
    g_Bh[idx] = h;
    g_Bl[idx] = __float2half_rn(v - __half2float(h));
}

// ---------------- mma.sync GEMM ----------------
#define SA_H 0
#define SA_L 32768
#define SB_H 65536
#define SB_L 98304
#define GSMEM 131072

__device__ __forceinline__ void load_tile(char* dstbase, const __half* g, int row0, int t) {
#pragma unroll
    for (int it = 0; it < 8; it++) {
        int cl = it * 256 + t;
        int row = cl >> 4, c = cl & 15;
        uint4 v = *(const uint4*)(g + (size_t)(row0 + row) * 128 + c * 8);
        *(uint4*)(dstbase + row * 256 + ((c ^ (row & 7)) * 16)) = v;
    }
}

__global__ __launch_bounds__(256) void k_gemm() {
    extern __shared__ char smem[];
    int t = threadIdx.x, lane = t & 31, w = t >> 5;
    int bx = blockIdx.x;
    int n0 = bx * 128, m0 = blockIdx.y * 128;

    load_tile(smem + SA_H, g_Ah, m0, t);
    load_tile(smem + SA_L, g_Al, m0, t);
    load_tile(smem + SB_H, g_Bh, n0, t);
    load_tile(smem + SB_L, g_Bl, n0, t);
    __syncthreads();

    int wm = (w & 1) * 64, wn = (w >> 1) * 32;
    float acc[4][4][4];
#pragma unroll
    for (int i = 0; i < 4; i++)
#pragma unroll
        for (int j = 0; j < 4; j++)
#pragma unroll
            for (int q = 0; q < 4; q++) acc[i][j][q] = 0.0f;

    uint32_t sbase = smem_u32(smem);
    int atile = lane >> 3, ar = lane & 7;
    int arow_base = wm + ((atile & 1) << 3) + ar;
    int achunk_sel = atile >> 1;
    int bl = lane & 15;
    int bhalf = bl >> 3, br = bl & 7;

#pragma unroll
    for (int pass = 0; pass < 3; pass++) {
        uint32_t abase = sbase + ((pass == 1) ? SA_L : SA_H);
        uint32_t bbase = sbase + ((pass == 2) ? SB_L : SB_H);
#pragma unroll
        for (int ks = 0; ks < 8; ks++) {
            uint32_t a[4][4];
            uint32_t b[4][2];
            int ac = ks * 2 + achunk_sel;
#pragma unroll
            for (int i = 0; i < 4; i++) {
                int row = arow_base + i * 16;
                uint32_t addr = abase + row * 256 + ((ac ^ (row & 7)) * 16);
                ldm_x4(a[i][0], a[i][1], a[i][2], a[i][3], addr);
            }
            int bc = ks * 2 + bhalf;
#pragma unroll
            for (int j = 0; j < 4; j++) {
                int row = wn + j * 8 + br;
                uint32_t addr = bbase + row * 256 + ((bc ^ (row & 7)) * 16);
                ldm_x2(b[j][0], b[j][1], addr);
            }
#pragma unroll
            for (int i = 0; i < 4; i++)
#pragma unroll
                for (int j = 0; j < 4; j++)
                    mma16816(acc[i][j], a[i][0], a[i][1], a[i][2], a[i][3], b[j][0], b[j][1]);
        }
    }
    __syncthreads();

    if (bx < 16) {
        __half* cs = (__half*)smem;
#pragma unroll
        for (int i = 0; i < 4; i++) {
#pragma unroll
            for (int j = 0; j < 4; j++) {
                int r = wm + i * 16 + (lane >> 2);
                int c = wn + j * 8 + 2 * (lane & 3);
                *(__half2*)(cs + r * 136 + c) = __floats2half2_rn(acc[i][j][0], acc[i][j][1]);
                *(__half2*)(cs + (r + 8) * 136 + c) = __floats2half2_rn(acc[i][j][2], acc[i][j][3]);
            }
        }
        __syncthreads();
#pragma unroll
        for (int it = 0; it < 8; it++) {
            int idx = it * 256 + t;
            int row = idx >> 4, ch = idx & 15;
            uint4 v = *(const uint4*)(cs + row * 136 + ch * 8);
            *(uint4*)(g_trans16 + (size_t)(m0 + row) * 2048 + n0 + ch * 8) = v;
        }
    } else {
        float* cs = (float*)smem;
#pragma unroll
        for (int i = 0; i < 4; i++) {
#pragma unroll
            for (int j = 0; j < 4; j++) {
                int r = wm + i * 16 + (lane >> 2);
                int c = wn + j * 8 + 2 * (lane & 3);
                *(float2*)(cs + r * 136 + c) = make_float2(acc[i][j][0], acc[i][j][1]);
                *(float2*)(cs + (r + 8) * 136 + c) = make_float2(acc[i][j][2], acc[i][j][3]);
            }
        }
        __syncthreads();
#pragma unroll
        for (int it = 0; it < 16; it++) {
            int idx = it * 256 + t;
            int row = idx >> 5, c4 = (idx & 31) * 4;
            float4 v = *(const float4*)(cs + row * 136 + c4);
            *(float4*)(g_self + (size_t)(m0 + row) * 128 + c4) = v;
        }
    }
}

// ---------------- fused gather + update: one warp per node ----------------
// agg = sum over in-edges of trans16[src][r*128:]; v = relu(self+b+agg/deg); LayerNorm.
__global__ __launch_bounds__(256) void k_gather(const float* __restrict__ bself,
                                                const float* __restrict__ lg,
                                                const float* __restrict__ lb,
                                                float* __restrict__ enc_out,
                                                int layer, int M) {
    int n = blockIdx.x * 8 + (threadIdx.x >> 5);
    int lane = threadIdx.x & 31;
    if (n >= M) return;
    int beg = g_off[n], end = g_off[n + 1];

    float a0 = 0.f, a1 = 0.f, a2 = 0.f, a3 = 0.f;
    int e = beg;
    for (; e + 2 <= end; e += 2) {
        uint32_t p0 = g_sed[e], p1 = g_sed[e + 1];
        const __half* m0p = g_trans16 + (size_t)(p0 & 0xFFFF) * 2048 + ((p0 >> 16) << 7) + lane * 4;
        const __half* m1p = g_trans16 + (size_t)(p1 & 0xFFFF) * 2048 + ((p1 >> 16) << 7) + lane * 4;
        uint2 r0 = *(const uint2*)m0p;
        uint2 r1 = *(const uint2*)m1p;
        float2 x0 = __half22float2(u32_as_h2(r0.x)), x1 = __half22float2(u32_as_h2(r0.y));
        float2 y0 = __half22float2(u32_as_h2(r1.x)), y1 = __half22float2(u32_as_h2(r1.y));
        a0 += x0.x + y0.x; a1 += x0.y + y0.y;
        a2 += x1.x + y1.x; a3 += x1.y + y1.y;
    }
    if (e < end) {
        uint32_t p0 = g_sed[e];
        const __half* m0p = g_trans16 + (size_t)(p0 & 0xFFFF) * 2048 + ((p0 >> 16) << 7) + lane * 4;
        uint2 r0 = *(const uint2*)m0p;
        float2 x0 = __half22float2(u32_as_h2(r0.x)), x1 = __half22float2(u32_as_h2(r0.y));
        a0 += x0.x; a1 += x0.y; a2 += x1.x; a3 += x1.y;
    }

    float inv_deg = 1.0f / fmaxf((float)(end - beg), 1.0f);
    float4 sv = *(const float4*)(g_self + (size_t)n * 128 + lane * 4);
    float4 bv = *(const float4*)(bself + lane * 4);
    float v0 = fmaxf(sv.x + bv.x + a0 * inv_deg, 0.f);
    float v1 = fmaxf(sv.y + bv.y + a1 * inv_deg, 0.f);
    float v2 = fmaxf(sv.z + bv.z + a2 * inv_deg, 0.f);
    float v3 = fmaxf(sv.w + bv.w + a3 * inv_deg, 0.f);

    float s = v0 + v1 + v2 + v3;
#pragma unroll
    for (int o = 16; o > 0; o >>= 1) s += __shfl_xor_sync(0xFFFFFFFFu, s, o);
    float mu = s * (1.0f / 128.0f);
    float d0 = v0 - mu, d1 = v1 - mu, d2 = v2 - mu, d3 = v3 - mu;
    float q = d0 * d0 + d1 * d1 + d2 * d2 + d3 * d3;
#pragma unroll
    for (int o = 16; o > 0; o >>= 1) q += __shfl_xor_sync(0xFFFFFFFFu, q, o);
    float rstd = rsqrtf(q * (1.0f / 128.0f) + 1e-5f);

    float4 gv = *(const float4*)(lg + lane * 4);
    float4 bv2 = *(const float4*)(lb + lane * 4);
    float4 ov = make_float4(d0 * rstd * gv.x + bv2.x, d1 * rstd * gv.y + bv2.y,
                            d2 * rstd * gv.z + bv2.z, d3 * rstd * gv.w + bv2.w);
    float* op = (layer == 0) ? (g_x + (size_t)n * 128 + lane * 4)
                             : (enc_out + (size_t)n * 128 + lane * 4);
    *(float4*)op = ov;
}

// ---------------- build LSTM input sequence ----------------
__global__ void k_seq(const float* __restrict__ enc, const int* __restrict__ pn,
                      const int* __restrict__ pr, const float* __restrict__ rel) {
    int pl = blockIdx.x;          // P*L blocks
    int p = pl >> 2, t = pl & 3;
    int d = threadIdx.x;          // 128
    int node = pn[p * 4 + t];
    float* o = g_seq + ((size_t)p * 4 + t) * 256;
    o[d] = enc[(size_t)node * 128 + d];
    float rv = 0.0f;
    if (t > 0) { int r = pr[p * 3 + (t - 1)]; rv = rel[r * 128 + d]; }
    o[128 + d] = rv;
}

// transpose LSTM weights: WT[dir][d][j]
__global__ void k_wt(const float* __restrict__ Wih_f, const float* __restrict__ Whh_f,
                     const float* __restrict__ Wih_b, const float* __restrict__ Whh_b) {
    int idx = blockIdx.x * blockDim.x + threadIdx.x;
    if (idx >= 2 * 384 * 512) return;
    int dir = idx / (384 * 512);
    int rem = idx % (384 * 512);
    int d = rem / 512, j = rem % 512;
    const float* Wih = dir ? Wih_b : Wih_f;
    const float* Whh = dir ? Whh_b : Whh_f;
    float v = (d < 256) ? Wih[j * 256 + d] : Whh[j * 128 + (d - 256)];
    g_WT[dir][rem] = v;
}

// ---------------- bidirectional LSTM (8 paths per block) ----------------
__global__ __launch_bounds__(512) void k_lstm(const float* __restrict__ bf,
                                              const float* __restrict__ bb) {
    const int PB = 8;
    __shared__ float xt[PB][256];
    __shared__ float hs[PB][128];
    __shared__ float cs[PB][128];
    __shared__ float gs[PB][512];
    int dir = blockIdx.y;
    const float* WT = g_WT[dir];
    const float* bias = dir ? bb : bf;
    int p0 = blockIdx.x * PB;
    int t = threadIdx.x;

    for (int i = t; i < PB * 128; i += 512) { ((float*)hs)[i] = 0.0f; ((float*)cs)[i] = 0.0f; }
    float bj = bias[t];
    __syncthreads();

    for (int step = 0; step < 4; step++) {
        int tt = dir ? (3 - step) : step;
        for (int i = t; i < PB * 256; i += 512) {
            int pp = i >> 8, d = i & 255;
            xt[pp][d] = g_seq[((size_t)(p0 + pp) * 4 + tt) * 256 + d];
        }
        __syncthreads();
        float acc[PB];
#pragma unroll
        for (int p = 0; p < PB; p++) acc[p] = bj;
        for (int d = 0; d < 256; d++) {
            float w = WT[d * 512 + t];
#pragma unroll
            for (int p = 0; p < PB; p++) acc[p] = fmaf(w, xt[p][d], acc[p]);
        }
        for (int d = 0; d < 128; d++) {
            float w = WT[(256 + d) * 512 + t];
#pragma unroll
            for (int p = 0; p < PB; p++) acc[p] = fmaf(w, hs[p][d], acc[p]);
        }
#pragma unroll
        for (int p = 0; p < PB; p++) gs[p][t] = acc[p];
        __syncthreads();
        for (int i = t; i < PB * 128; i += 512) {
            int pp = i >> 7, k = i & 127;
            float ig = 1.0f / (1.0f + expf(-gs[pp][k]));
            float fg = 1.0f / (1.0f + expf(-gs[pp][128 + k]));
            float gg = tanhf(gs[pp][256 + k]);
            float og = 1.0f / (1.0f + expf(-gs[pp][384 + k]));
            float c = fg * cs[pp][k] + ig * gg;
            cs[pp][k] = c;
            hs[pp][k] = og * tanhf(c);
        }
        __syncthreads();
    }
    for (int i = t; i < PB * 128; i += 512) {
        int pp = i >> 7, k = i & 127;
        g_h[((size_t)dir * 256 + p0 + pp) * 128 + k] = hs[pp][k];
    }
}

// ---------------- output head ----------------
__global__ void k_head(const float* __restrict__ Wop, const float* __restrict__ bop,
                       const float* __restrict__ q, const float* __restrict__ Ws1,
                       const float* __restrict__ bs1, const float* __restrict__ Ws2,
                       const float* __restrict__ bs2,
                       float* __restrict__ pe_out, float* __restrict__ sim_out) {
    int p = blockIdx.x;
    int k = threadIdx.x;   // 128
    __shared__ float cat[256];
    __shared__ float cat2[256];
    __shared__ float red[4];
    cat[k]       = g_h[(size_t)p * 128 + k];
    cat[128 + k] = g_h[(size_t)(256 + p) * 128 + k];
    __syncthreads();
    float acc = bop[k];
    for (int j = 0; j < 256; j++) acc = fmaf(cat[j], Wop[k * 256 + j], acc);
    float pe = fmaxf(acc, 0.0f);
    pe_out[(size_t)p * 128 + k] = pe;
    cat2[k] = pe;
    cat2[128 + k] = q[k];
    __syncthreads();
    float a2 = bs1[k];
    for (int j = 0; j < 256; j++) a2 = fmaf(cat2[j], Ws1[k * 256 + j], a2);
    float hdn = fmaxf(a2, 0.0f);
    float s = hdn * Ws2[k];
#pragma unroll
    for (int o = 16; o > 0; o >>= 1) s += __shfl_xor_sync(0xFFFFFFFFu, s, o);
    if ((k & 31) == 0) red[k >> 5] = s;
    __syncthreads();
    if (k == 0) {
        float tot = red[0] + red[1] + red[2] + red[3] + bs2[0];
        sim_out[p] = 1.0f / (1.0f + expf(-tot));
    }
}

// ---------------- launch ----------------
extern "C" void kernel_launch(void* const* d_in, const int* in_sizes, int n_in,
                              void* d_out, int out_size) {
    const float* node_features = (const float*)d_in[0];
    const int*   edge_index    = (const int*)d_in[1];
    const int*   edge_types    = (const int*)d_in[2];
    const float* query         = (const float*)d_in[3];
    const int*   path_nodes    = (const int*)d_in[4];
    const int*   path_rel      = (const int*)d_in[5];
    const float* W_self        = (const float*)d_in[6];
    const float* b_self        = (const float*)d_in[7];
    const float* W_rel         = (const float*)d_in[8];
    const float* ln_g          = (const float*)d_in[9];
    const float* ln_b          = (const float*)d_in[10];
    const float* rel_emb       = (const float*)d_in[11];
    const float* W_ih_f        = (const float*)d_in[12];
    const float* W_hh_f        = (const float*)d_in[13];
    const float* b_f           = (const float*)d_in[14];
    const float* W_ih_b        = (const float*)d_in[15];
    const float* W_hh_b        = (const float*)d_in[16];
    const float* b_b           = (const float*)d_in[17];
    const float* W_op          = (const float*)d_in[18];
    const float* b_op          = (const float*)d_in[19];
    const float* W_s1          = (const float*)d_in[20];
    const float* b_s1          = (const float*)d_in[21];
    const float* W_s2          = (const float*)d_in[22];
    const float* b_s2          = (const float*)d_in[23];
    (void)n_in; (void)out_size;

    const int N = in_sizes[0] / 128;   // 50000
    const int E = in_sizes[1] / 2;     // 800000
    const int P = in_sizes[4] / 4;     // 256

    float* out     = (float*)d_out;
    float* enc_out = out;
    float* pe_out  = out + (size_t)N * 128;
    float* sim_out = pe_out + (size_t)P * 128;

    const int* src = edge_index;
    const int* dst = edge_index + E;

    cudaFuncSetAttribute(k_gemm, cudaFuncAttributeMaxDynamicSharedMemorySize, GSMEM);

    // CSR build (once per call)
    k_zero_cnt<<<(N + 255) / 256, 256>>>(N);
    k_hist<<<(E + 255) / 256, 256>>>(dst, E);
    k_scan<<<1, 1024>>>(N);
    k_place<<<(E + 255) / 256, 256>>>(src, dst, edge_types, E);

    for (int l = 0; l < 2; l++) {
        k_conv<<<(MPAD * 32 + 255) / 256, 256>>>(node_features, l, N);
        k_packb<<<(NCOL * 128 + 255) / 256, 256>>>(W_rel + (size_t)l * R * 128 * 128,
                                                   W_self + (size_t)l * 128 * 128);
        dim3 ggrid(NCOL / 128, MPAD / 128);
        k_gemm<<<ggrid, 256, GSMEM>>>();
        k_gather<<<(N + 7) / 8, 256>>>(b_self + l * 128, ln_g + l * 128, ln_b + l * 128,
                                       enc_out, l, N);
    }

    k_seq<<<P * 4, 128>>>(enc_out, path_nodes, path_rel, rel_emb);
    k_wt<<<(2 * 384 * 512 + 255) / 256, 256>>>(W_ih_f, W_hh_f, W_ih_b, W_hh_b);
    k_lstm<<<dim3(P / 8, 2), 512>>>(b_f, b_b);
    k_head<<<P, 128>>>(W_op, b_op, query, W_s1, b_s1, W_s2, b_s2, pe_out, sim_out);
}

// round 7
// speedup vs baseline: 2.7086x; 1.3189x over previous
#include <cuda_runtime.h>
#include <cuda_fp16.h>
#include <math.h>
#include <stdint.h>

#define D 128
#define R 16
#define NCOL 2176
#define MPAD 50048         // 391 * 128
#define NMAX 50000
#define EMAX 800000

// ---------------- scratch (device globals; allocation-free) ----------------
__device__ __half g_trans16[(size_t)MPAD * 2048];  // 204 MB, relation messages
__device__ float g_self[(size_t)MPAD * 128];
__device__ float g_x[(size_t)MPAD * 128];
__device__ __half g_Ah[(size_t)MPAD * 128];
__device__ __half g_Al[(size_t)MPAD * 128];
__device__ __half g_Bh[NCOL * 128];                 // [n][k]
__device__ float g_seq[256 * 4 * 256];
__device__ float g_WT[2][384 * 512];
__device__ float g_h[2 * 256 * 128];
// CSR
__device__ int g_cnt[NMAX];
__device__ int g_off[NMAX + 1];
__device__ int g_cur[NMAX];
__device__ uint32_t g_sed[EMAX];   // packed src | (r<<16)

// ---------------- bit-cast helpers ----------------
__device__ __forceinline__ uint32_t h2_as_u32(__half2 h) {
    uint32_t u; *(__half2*)&u = h; return u;
}
__device__ __forceinline__ __half2 u32_as_h2(uint32_t u) {
    __half2 h; *(uint32_t*)&h = u; return h;
}

// ---------------- PTX helpers ----------------
__device__ __forceinline__ uint32_t smem_u32(const void* p) {
    return (uint32_t)__cvta_generic_to_shared(p);
}
__device__ __forceinline__ void ldm_x4(uint32_t& r0, uint32_t& r1, uint32_t& r2, uint32_t& r3,
                                       uint32_t a) {
    asm volatile("ldmatrix.sync.aligned.m8n8.x4.shared.b16 {%0,%1,%2,%3}, [%4];"
                 : "=r"(r0), "=r"(r1), "=r"(r2), "=r"(r3) : "r"(a));
}
__device__ __forceinline__ void ldm_x2(uint32_t& r0, uint32_t& r1, uint32_t a) {
    asm volatile("ldmatrix.sync.aligned.m8n8.x2.shared.b16 {%0,%1}, [%2];"
                 : "=r"(r0), "=r"(r1) : "r"(a));
}
__device__ __forceinline__ void mma16816(float* c, uint32_t a0, uint32_t a1, uint32_t a2,
                                         uint32_t a3, uint32_t b0, uint32_t b1) {
    asm volatile(
        "mma.sync.aligned.m16n8k16.row.col.f32.f16.f16.f32 "
        "{%0,%1,%2,%3}, {%4,%5,%6,%7}, {%8,%9}, {%0,%1,%2,%3};"
        : "+f"(c[0]), "+f"(c[1]), "+f"(c[2]), "+f"(c[3])
        : "r"(a0), "r"(a1), "r"(a2), "r"(a3), "r"(b0), "r"(b1));
}

// ---------------- CSR build ----------------
__global__ void k_zero_cnt(int N) {
    int i = blockIdx.x * blockDim.x + threadIdx.x;
    if (i < N) g_cnt[i] = 0;
}
__global__ void k_hist(const int* __restrict__ dst, int E) {
    int e = blockIdx.x * blockDim.x + threadIdx.x;
    if (e < E) atomicAdd(&g_cnt[dst[e]], 1);
}
__global__ __launch_bounds__(1024) void k_scan(int N) {
    __shared__ int sh[1024];
    int t = threadIdx.x;
    int chunk = (N + 1023) / 1024;
    int c0 = t * chunk, c1 = min(c0 + chunk, N);
    int s = 0;
    for (int i = c0; i < c1; i++) s += g_cnt[i];
    sh[t] = s;
    __syncthreads();
    for (int o = 1; o < 1024; o <<= 1) {
        int v = (t >= o) ? sh[t - o] : 0;
        __syncthreads();
        sh[t] += v;
        __syncthreads();
    }
    int run = sh[t] - s;
    for (int i = c0; i < c1; i++) {
        g_off[i] = run;
        g_cur[i] = run;
        run += g_cnt[i];
    }
    if (t == 1023) g_off[N] = run;
}
__global__ void k_place(const int* __restrict__ src, const int* __restrict__ dst,
                        const int* __restrict__ et, int E) {
    int e = blockIdx.x * blockDim.x + threadIdx.x;
    if (e >= E) return;
    int pos = atomicAdd(&g_cur[dst[e]], 1);
    g_sed[pos] = (uint32_t)src[e] | ((uint32_t)et[e] << 16);
}

// ---------------- conversions ----------------
__global__ void k_conv(const float* __restrict__ x0, int layer, int Nn) {
    int i4 = blockIdx.x * blockDim.x + threadIdx.x;
    if (i4 >= MPAD * 32) return;
    const float* src = (layer == 0) ? x0 : (const float*)g_x;
    int row = i4 >> 5;
    float4 v = make_float4(0.f, 0.f, 0.f, 0.f);
    if (row < Nn) v = *(const float4*)(src + (size_t)i4 * 4);
    __half2 h0 = __floats2half2_rn(v.x, v.y);
    __half2 h1 = __floats2half2_rn(v.z, v.w);
    float2 f0 = __half22float2(h0), f1 = __half22float2(h1);
    __half2 l0 = __floats2half2_rn(v.x - f0.x, v.y - f0.y);
    __half2 l1 = __floats2half2_rn(v.z - f1.x, v.w - f1.y);
    ((uint2*)g_Ah)[i4] = make_uint2(h2_as_u32(h0), h2_as_u32(h1));
    ((uint2*)g_Al)[i4] = make_uint2(h2_as_u32(l0), h2_as_u32(l1));
}

__global__ void k_packb(const float* __restrict__ Wrel, const float* __restrict__ Wself) {
    int idx = blockIdx.x * blockDim.x + threadIdx.x;
    if (idx >= NCOL * 128) return;
    int n = idx >> 7, d = idx & 127;
    float v;
    if (n < 2048) {
        int r = n >> 7, k = n & 127;
        v = Wrel[((size_t)r * 128 + d) * 128 + k];
    } else {
        v = Wself[d * 128 + (n - 2048)];
    }
    g_Bh[idx] = __float2half_rn(v);
}

// ---------------- A-resident pipelined GEMM ----------------
// One CTA per 128-row m-tile; A (hi+lo) resident in smem; loop 17 n-tiles with
// double-buffered cp.async B loads. 2 passes: Ah*Bh + Al*Bh.
#define SM_AH 0
#define SM_AL 32768
#define SM_B0 65536
#define SM_B1 98304
#define SM_C  131072
#define GSMEM (131072 + 69632)   // + 128*136*4 C staging

__device__ __forceinline__ void load_tile(char* dstbase, const __half* g, int row0, int t) {
#pragma unroll
    for (int it = 0; it < 8; it++) {
        int cl = it * 256 + t;
        int row = cl >> 4, c = cl & 15;
        uint4 v = *(const uint4*)(g + (size_t)(row0 + row) * 128 + c * 8);
        *(uint4*)(dstbase + row * 256 + ((c ^ (row & 7)) * 16)) = v;
    }
}

__device__ __forceinline__ void prefetch_b(uint32_t dstb, const __half* gsrc, int t) {
#pragma unroll
    for (int it = 0; it < 8; it++) {
        int cl = it * 256 + t;
        int row = cl >> 4, c = cl & 15;
        const void* src = gsrc + (size_t)row * 128 + c * 8;
        uint32_t dst = dstb + row * 256 + ((c ^ (row & 7)) * 16);
        asm volatile("cp.async.cg.shared.global [%0], [%1], 16;" :: "r"(dst), "l"(src));
    }
    asm volatile("cp.async.commit_group;");
}

__global__ __launch_bounds__(256, 1) void k_gemm() {
    extern __shared__ char smem[];
    int t = threadIdx.x, lane = t & 31, w = t >> 5;
    int m0 = blockIdx.x * 128;
    uint32_t sbase = smem_u32(smem);

    prefetch_b(sbase + SM_B0, g_Bh, t);
    load_tile(smem + SM_AH, g_Ah, m0, t);
    load_tile(smem + SM_AL, g_Al, m0, t);

    int wm = (w & 1) * 64, wn = (w >> 1) * 32;
    int atile = lane >> 3, ar = lane & 7;
    int arow_base = wm + ((atile & 1) << 3) + ar;
    int achunk_sel = atile >> 1;
    int bl = lane & 15;
    int bhalf = bl >> 3, br = bl & 7;

    for (int n = 0; n < 17; n++) {
        uint32_t bbase = sbase + ((n & 1) ? SM_B1 : SM_B0);
        asm volatile("cp.async.wait_group 0;");
        __syncthreads();
        if (n + 1 < 17) {
            prefetch_b(sbase + (((n + 1) & 1) ? SM_B1 : SM_B0),
                       g_Bh + (size_t)(n + 1) * 128 * 128, t);
        }

        float acc[4][4][4];
#pragma unroll
        for (int i = 0; i < 4; i++)
#pragma unroll
            for (int j = 0; j < 4; j++)
#pragma unroll
                for (int q = 0; q < 4; q++) acc[i][j][q] = 0.0f;

#pragma unroll
        for (int pass = 0; pass < 2; pass++) {
            uint32_t abase = sbase + (pass ? SM_AL : SM_AH);
#pragma unroll
            for (int ks = 0; ks < 8; ks++) {
                uint32_t a[4][4];
                uint32_t b[4][2];
                int ac = ks * 2 + achunk_sel;
#pragma unroll
                for (int i = 0; i < 4; i++) {
                    int row = arow_base + i * 16;
                    uint32_t addr = abase + row * 256 + ((ac ^ (row & 7)) * 16);
                    ldm_x4(a[i][0], a[i][1], a[i][2], a[i][3], addr);
                }
                int bc = ks * 2 + bhalf;
#pragma unroll
                for (int j = 0; j < 4; j++) {
                    int row = wn + j * 8 + br;
                    uint32_t addr = bbase + row * 256 + ((bc ^ (row & 7)) * 16);
                    ldm_x2(b[j][0], b[j][1], addr);
                }
#pragma unroll
                for (int i = 0; i < 4; i++)
#pragma unroll
                    for (int j = 0; j < 4; j++)
                        mma16816(acc[i][j], a[i][0], a[i][1], a[i][2], a[i][3], b[j][0], b[j][1]);
            }
        }
        __syncthreads();   // previous epilogue readers done (also covered by top sync)

        // stage C in smem (fp32, stride 136 floats)
        float* cs = (float*)(smem + SM_C);
#pragma unroll
        for (int i = 0; i < 4; i++) {
#pragma unroll
            for (int j = 0; j < 4; j++) {
                int r = wm + i * 16 + (lane >> 2);
                int c = wn + j * 8 + 2 * (lane & 3);
                *(float2*)(cs + r * 136 + c) = make_float2(acc[i][j][0], acc[i][j][1]);
                *(float2*)(cs + (r + 8) * 136 + c) = make_float2(acc[i][j][2], acc[i][j][3]);
            }
        }
        __syncthreads();

        if (n < 16) {
#pragma unroll
            for (int it = 0; it < 16; it++) {
                int idx = it * 256 + t;            // 4096: 128 rows x 32 float4-chunks
                int row = idx >> 5, c4 = (idx & 31) * 4;
                float4 v = *(const float4*)(cs + row * 136 + c4);
                __half2 h0 = __floats2half2_rn(v.x, v.y);
                __half2 h1 = __floats2half2_rn(v.z, v.w);
                *(uint2*)(g_trans16 + (size_t)(m0 + row) * 2048 + n * 128 + c4) =
                    make_uint2(h2_as_u32(h0), h2_as_u32(h1));
            }
        } else {
#pragma unroll
            for (int it = 0; it < 16; it++) {
                int idx = it * 256 + t;
                int row = idx >> 5, c4 = (idx & 31) * 4;
                float4 v = *(const float4*)(cs + row * 136 + c4);
                *(float4*)(g_self + (size_t)(m0 + row) * 128 + c4) = v;
            }
        }
    }
}

// ---------------- fused gather + update: one warp per node ----------------
__global__ __launch_bounds__(256) void k_gather(const float* __restrict__ bself,
                                                const float* __restrict__ lg,
                                                const float* __restrict__ lb,
                                                float* __restrict__ enc_out,
                                                int layer, int M) {
    int n = blockIdx.x * 8 + (threadIdx.x >> 5);
    int lane = threadIdx.x & 31;
    if (n >= M) return;
    int beg = g_off[n], end = g_off[n + 1];

    float a0 = 0.f, a1 = 0.f, a2 = 0.f, a3 = 0.f;
    int e = beg;
    for (; e + 4 <= end; e += 4) {
        uint32_t p0 = g_sed[e], p1 = g_sed[e + 1], p2 = g_sed[e + 2], p3 = g_sed[e + 3];
        uint2 r0 = *(const uint2*)(g_trans16 + (size_t)(p0 & 0xFFFF) * 2048 + ((p0 >> 16) << 7) + lane * 4);
        uint2 r1 = *(const uint2*)(g_trans16 + (size_t)(p1 & 0xFFFF) * 2048 + ((p1 >> 16) << 7) + lane * 4);
        uint2 r2 = *(const uint2*)(g_trans16 + (size_t)(p2 & 0xFFFF) * 2048 + ((p2 >> 16) << 7) + lane * 4);
        uint2 r3 = *(const uint2*)(g_trans16 + (size_t)(p3 & 0xFFFF) * 2048 + ((p3 >> 16) << 7) + lane * 4);
        float2 x0 = __half22float2(u32_as_h2(r0.x)), x1 = __half22float2(u32_as_h2(r0.y));
        float2 y0 = __half22float2(u32_as_h2(r1.x)), y1 = __half22float2(u32_as_h2(r1.y));
        float2 z0 = __half22float2(u32_as_h2(r2.x)), z1 = __half22float2(u32_as_h2(r2.y));
        float2 w0 = __half22float2(u32_as_h2(r3.x)), w1 = __half22float2(u32_as_h2(r3.y));
        a0 += (x0.x + y0.x) + (z0.x + w0.x);
        a1 += (x0.y + y0.y) + (z0.y + w0.y);
        a2 += (x1.x + y1.x) + (z1.x + w1.x);
        a3 += (x1.y + y1.y) + (z1.y + w1.y);
    }
    for (; e < end; e++) {
        uint32_t p0 = g_sed[e];
        uint2 r0 = *(const uint2*)(g_trans16 + (size_t)(p0 & 0xFFFF) * 2048 + ((p0 >> 16) << 7) + lane * 4);
        float2 x0 = __half22float2(u32_as_h2(r0.x)), x1 = __half22float2(u32_as_h2(r0.y));
        a0 += x0.x; a1 += x0.y; a2 += x1.x; a3 += x1.y;
    }

    float inv_deg = 1.0f / fmaxf((float)(end - beg), 1.0f);
    float4 sv = *(const float4*)(g_self + (size_t)n * 128 + lane * 4);
    float4 bv = *(const float4*)(bself + lane * 4);
    float v0 = fmaxf(sv.x + bv.x + a0 * inv_deg, 0.f);
    float v1 = fmaxf(sv.y + bv.y + a1 * inv_deg, 0.f);
    float v2 = fmaxf(sv.z + bv.z + a2 * inv_deg, 0.f);
    float v3 = fmaxf(sv.w + bv.w + a3 * inv_deg, 0.f);

    float s = v0 + v1 + v2 + v3;
#pragma unroll
    for (int o = 16; o > 0; o >>= 1) s += __shfl_xor_sync(0xFFFFFFFFu, s, o);
    float mu = s * (1.0f / 128.0f);
    float d0 = v0 - mu, d1 = v1 - mu, d2 = v2 - mu, d3 = v3 - mu;
    float q = d0 * d0 + d1 * d1 + d2 * d2 + d3 * d3;
#pragma unroll
    for (int o = 16; o > 0; o >>= 1) q += __shfl_xor_sync(0xFFFFFFFFu, q, o);
    float rstd = rsqrtf(q * (1.0f / 128.0f) + 1e-5f);

    float4 gv = *(const float4*)(lg + lane * 4);
    float4 bv2 = *(const float4*)(lb + lane * 4);
    float4 ov = make_float4(d0 * rstd * gv.x + bv2.x, d1 * rstd * gv.y + bv2.y,
                            d2 * rstd * gv.z + bv2.z, d3 * rstd * gv.w + bv2.w);
    float* op = (layer == 0) ? (g_x + (size_t)n * 128 + lane * 4)
                             : (enc_out + (size_t)n * 128 + lane * 4);
    *(float4*)op = ov;
}

// ---------------- build LSTM input sequence ----------------
__global__ void k_seq(const float* __restrict__ enc, const int* __restrict__ pn,
                      const int* __restrict__ pr, const float* __restrict__ rel) {
    int pl = blockIdx.x;
    int p = pl >> 2, t = pl & 3;
    int d = threadIdx.x;
    int node = pn[p * 4 + t];
    float* o = g_seq + ((size_t)p * 4 + t) * 256;
    o[d] = enc[(size_t)node * 128 + d];
    float rv = 0.0f;
    if (t > 0) { int r = pr[p * 3 + (t - 1)]; rv = rel[r * 128 + d]; }
    o[128 + d] = rv;
}

__global__ void k_wt(const float* __restrict__ Wih_f, const float* __restrict__ Whh_f,
                     const float* __restrict__ Wih_b, const float* __restrict__ Whh_b) {
    int idx = blockIdx.x * blockDim.x + threadIdx.x;
    if (idx >= 2 * 384 * 512) return;
    int dir = idx / (384 * 512);
    int rem = idx % (384 * 512);
    int d = rem / 512, j = rem % 512;
    const float* Wih = dir ? Wih_b : Wih_f;
    const float* Whh = dir ? Whh_b : Whh_f;
    float v = (d < 256) ? Wih[j * 256 + d] : Whh[j * 128 + (d - 256)];
    g_WT[dir][rem] = v;
}

// ---------------- bidirectional LSTM (8 paths per block) ----------------
__global__ __launch_bounds__(512) void k_lstm(const float* __restrict__ bf,
                                              const float* __restrict__ bb) {
    const int PB = 8;
    __shared__ float xt[PB][256];
    __shared__ float hs[PB][128];
    __shared__ float cs[PB][128];
    __shared__ float gs[PB][512];
    int dir = blockIdx.y;
    const float* WT = g_WT[dir];
    const float* bias = dir ? bb : bf;
    int p0 = blockIdx.x * PB;
    int t = threadIdx.x;

    for (int i = t; i < PB * 128; i += 512) { ((float*)hs)[i] = 0.0f; ((float*)cs)[i] = 0.0f; }
    float bj = bias[t];
    __syncthreads();

    for (int step = 0; step < 4; step++) {
        int tt = dir ? (3 - step) : step;
        for (int i = t; i < PB * 256; i += 512) {
            int pp = i >> 8, d = i & 255;
            xt[pp][d] = g_seq[((size_t)(p0 + pp) * 4 + tt) * 256 + d];
        }
        __syncthreads();
        float acc[PB];
#pragma unroll
        for (int p = 0; p < PB; p++) acc[p] = bj;
        for (int d = 0; d < 256; d++) {
            float w = WT[d * 512 + t];
#pragma unroll
            for (int p = 0; p < PB; p++) acc[p] = fmaf(w, xt[p][d], acc[p]);
        }
        for (int d = 0; d < 128; d++) {
            float w = WT[(256 + d) * 512 + t];
#pragma unroll
            for (int p = 0; p < PB; p++) acc[p] = fmaf(w, hs[p][d], acc[p]);
        }
#pragma unroll
        for (int p = 0; p < PB; p++) gs[p][t] = acc[p];
        __syncthreads();
        for (int i = t; i < PB * 128; i += 512) {
            int pp = i >> 7, k = i & 127;
            float ig = 1.0f / (1.0f + expf(-gs[pp][k]));
            float fg = 1.0f / (1.0f + expf(-gs[pp][128 + k]));
            float gg = tanhf(gs[pp][256 + k]);
            float og = 1.0f / (1.0f + expf(-gs[pp][384 + k]));
            float c = fg * cs[pp][k] + ig * gg;
            cs[pp][k] = c;
            hs[pp][k] = og * tanhf(c);
        }
        __syncthreads();
    }
    for (int i = t; i < PB * 128; i += 512) {
        int pp = i >> 7, k = i & 127;
        g_h[((size_t)dir * 256 + p0 + pp) * 128 + k] = hs[pp][k];
    }
}

// ---------------- output head ----------------
__global__ void k_head(const float* __restrict__ Wop, const float* __restrict__ bop,
                       const float* __restrict__ q, const float* __restrict__ Ws1,
                       const float* __restrict__ bs1, const float* __restrict__ Ws2,
                       const float* __restrict__ bs2,
                       float* __restrict__ pe_out, float* __restrict__ sim_out) {
    int p = blockIdx.x;
    int k = threadIdx.x;
    __shared__ float cat[256];
    __shared__ float cat2[256];
    __shared__ float red[4];
    cat[k]       = g_h[(size_t)p * 128 + k];
    cat[128 + k] = g_h[(size_t)(256 + p) * 128 + k];
    __syncthreads();
    float acc = bop[k];
    for (int j = 0; j < 256; j++) acc = fmaf(cat[j], Wop[k * 256 + j], acc);
    float pe = fmaxf(acc, 0.0f);
    pe_out[(size_t)p * 128 + k] = pe;
    cat2[k] = pe;
    cat2[128 + k] = q[k];
    __syncthreads();
    float a2 = bs1[k];
    for (int j = 0; j < 256; j++) a2 = fmaf(cat2[j], Ws1[k * 256 + j], a2);
    float hdn = fmaxf(a2, 0.0f);
    float s = hdn * Ws2[k];
#pragma unroll
    for (int o = 16; o > 0; o >>= 1) s += __shfl_xor_sync(0xFFFFFFFFu, s, o);
    if ((k & 31) == 0) red[k >> 5] = s;
    __syncthreads();
    if (k == 0) {
        float tot = red[0] + red[1] + red[2] + red[3] + bs2[0];
        sim_out[p] = 1.0f / (1.0f + expf(-tot));
    }
}

// ---------------- launch ----------------
extern "C" void kernel_launch(void* const* d_in, const int* in_sizes, int n_in,
                              void* d_out, int out_size) {
    const float* node_features = (const float*)d_in[0];
    const int*   edge_index    = (const int*)d_in[1];
    const int*   edge_types    = (const int*)d_in[2];
    const float* query         = (const float*)d_in[3];
    const int*   path_nodes    = (const int*)d_in[4];
    const int*   path_rel      = (const int*)d_in[5];
    const float* W_self        = (const float*)d_in[6];
    const float* b_self        = (const float*)d_in[7];
    const float* W_rel         = (const float*)d_in[8];
    const float* ln_g          = (const float*)d_in[9];
    const float* ln_b          = (const float*)d_in[10];
    const float* rel_emb       = (const float*)d_in[11];
    const float* W_ih_f        = (const float*)d_in[12];
    const float* W_hh_f        = (const float*)d_in[13];
    const float* b_f           = (const float*)d_in[14];
    const float* W_ih_b        = (const float*)d_in[15];
    const float* W_hh_b        = (const float*)d_in[16];
    const float* b_b           = (const float*)d_in[17];
    const float* W_op          = (const float*)d_in[18];
    const float* b_op          = (const float*)d_in[19];
    const float* W_s1          = (const float*)d_in[20];
    const float* b_s1          = (const float*)d_in[21];
    const float* W_s2          = (const float*)d_in[22];
    const float* b_s2          = (const float*)d_in[23];
    (void)n_in; (void)out_size;

    const int N = in_sizes[0] / 128;
    const int E = in_sizes[1] / 2;
    const int P = in_sizes[4] / 4;

    float* out     = (float*)d_out;
    float* enc_out = out;
    float* pe_out  = out + (size_t)N * 128;
    float* sim_out = pe_out + (size_t)P * 128;

    const int* src = edge_index;
    const int* dst = edge_index + E;

    cudaFuncSetAttribute(k_gemm, cudaFuncAttributeMaxDynamicSharedMemorySize, GSMEM);

    // CSR build (once per call)
    k_zero_cnt<<<(N + 255) / 256, 256>>>(N);
    k_hist<<<(E + 255) / 256, 256>>>(dst, E);
    k_scan<<<1, 1024>>>(N);
    k_place<<<(E + 255) / 256, 256>>>(src, dst, edge_types, E);

    for (int l = 0; l < 2; l++) {
        k_conv<<<(MPAD * 32 + 255) / 256, 256>>>(node_features, l, N);
        k_packb<<<(NCOL * 128 + 255) / 256, 256>>>(W_rel + (size_t)l * R * 128 * 128,
                                                   W_self + (size_t)l * 128 * 128);
        k_gemm<<<MPAD / 128, 256, GSMEM>>>();
        k_gather<<<(N + 7) / 8, 256>>>(b_self + l * 128, ln_g + l * 128, ln_b + l * 128,
                                       enc_out, l, N);
    }

    k_seq<<<P * 4, 128>>>(enc_out, path_nodes, path_rel, rel_emb);
    k_wt<<<(2 * 384 * 512 + 255) / 256, 256>>>(W_ih_f, W_hh_f, W_ih_b, W_hh_b);
    k_lstm<<<dim3(P / 8, 2), 512>>>(b_f, b_b);
    k_head<<<P, 128>>>(W_op, b_op, query, W_s1, b_s1, W_s2, b_s2, pe_out, sim_out);
}